// round 1
// baseline (speedup 1.0000x reference)
#include <cuda_runtime.h>
#include <cstdint>

#define N_NODES 50000
#define NUM_E   1600000
#define IN_F    512
#define OUT_F   128
#define NEG_SLOPE 0.01f
#define INV_T     2.0f   // 1 / TEMPERATURE (0.5)

// ---------------- scratch (static device globals; no allocations) -----------
__device__ float    g_Wh[(size_t)N_NODES * OUT_F];   // 25.6 MB
__device__ float    g_s1[N_NODES];
__device__ float    g_s2[N_NODES];
__device__ unsigned g_segmax[N_NODES];               // order-preserving-uint encoded float max
__device__ float    g_denom[N_NODES];
__device__ int      g_is64;

// ---------------- helpers ----------------------------------------------------
__device__ __forceinline__ unsigned enc_f(float f) {
    unsigned b = __float_as_uint(f);
    return (b & 0x80000000u) ? ~b : (b | 0x80000000u);
}
__device__ __forceinline__ float dec_f(unsigned k) {
    return __uint_as_float((k & 0x80000000u) ? (k & 0x7FFFFFFFu) : ~k);
}
__device__ __forceinline__ float leaky_logit(float v) {
    v = (v >= 0.0f) ? v : NEG_SLOPE * v;
    return v * INV_T;
}

// ---------------- dtype detection for edge_index -----------------------------
// If the buffer is int64 (values < 50000, nonneg), every odd int32 word of the
// first 2048 is zero. For a random int32 array this is (1/50000)^2048 ~ 0.
__global__ void detect_kernel(const int* __restrict__ ei) {
    __shared__ int any;
    if (threadIdx.x == 0) any = 0;
    __syncthreads();
    for (int i = threadIdx.x; i < 2048; i += blockDim.x)
        if (ei[2 * i + 1] != 0) any = 1;
    __syncthreads();
    if (threadIdx.x == 0) g_is64 = any ? 0 : 1;
}

__device__ __forceinline__ void load_edge(const void* ei, int e, int& s, int& d) {
    if (g_is64) {
        const long long* p = (const long long*)ei;
        s = (int)p[e];
        d = (int)p[NUM_E + e];
    } else {
        const int* p = (const int*)ei;
        s = p[e];
        d = p[NUM_E + e];
    }
}

// ---------------- GEMM: Wh = h @ W  (fp32 SIMT, BM=64 BN=128 BK=32) ----------
#define BM 64
#define BN 128
#define BK 32

__global__ __launch_bounds__(256) void gemm_kernel(const float* __restrict__ h,
                                                   const float* __restrict__ W) {
    __shared__ float As[BK][BM];   // transposed A tile
    __shared__ float Bs[BK][BN];

    const int block_row = blockIdx.x * BM;
    const int tid = threadIdx.x;
    const int tx  = tid & 31;   // col group (0..31) -> cols tx*4..tx*4+3
    const int ty  = tid >> 5;   // row group (0..7)  -> rows ty*8..ty*8+7

    float acc[8][4];
    #pragma unroll
    for (int i = 0; i < 8; i++)
        #pragma unroll
        for (int j = 0; j < 4; j++) acc[i][j] = 0.0f;

    for (int k0 = 0; k0 < IN_F; k0 += BK) {
        // A tile: 64 rows x 32 k = 512 float4 loads; 2 per thread
        #pragma unroll
        for (int i = 0; i < 2; i++) {
            int t   = tid + i * 256;        // 0..511
            int row = t >> 3;               // 8 float4 per row
            int kc  = (t & 7) * 4;
            float4 v = make_float4(0.f, 0.f, 0.f, 0.f);
            int gr = block_row + row;
            if (gr < N_NODES)
                v = *(const float4*)&h[(size_t)gr * IN_F + k0 + kc];
            As[kc + 0][row] = v.x;
            As[kc + 1][row] = v.y;
            As[kc + 2][row] = v.z;
            As[kc + 3][row] = v.w;
        }
        // B tile: 32 k x 128 n = 1024 float4 loads; 4 per thread
        #pragma unroll
        for (int i = 0; i < 4; i++) {
            int t   = tid + i * 256;        // 0..1023
            int row = t >> 5;               // 32 float4 per row
            int nc  = (t & 31) * 4;
            *(float4*)&Bs[row][nc] = *(const float4*)&W[(size_t)(k0 + row) * OUT_F + nc];
        }
        __syncthreads();

        #pragma unroll
        for (int k = 0; k < BK; k++) {
            float b[4];
            *(float4*)b = *(const float4*)&Bs[k][tx * 4];
            float a0[8];
            *(float4*)&a0[0] = *(const float4*)&As[k][ty * 8];
            *(float4*)&a0[4] = *(const float4*)&As[k][ty * 8 + 4];
            #pragma unroll
            for (int i = 0; i < 8; i++)
                #pragma unroll
                for (int j = 0; j < 4; j++)
                    acc[i][j] += a0[i] * b[j];
        }
        __syncthreads();
    }

    #pragma unroll
    for (int i = 0; i < 8; i++) {
        int gr = block_row + ty * 8 + i;
        if (gr < N_NODES)
            *(float4*)&g_Wh[(size_t)gr * OUT_F + tx * 4] = *(float4*)&acc[i][0];
    }
}

// ---------------- s1/s2 = Wh @ a1, Wh @ a2 + per-node init -------------------
__global__ __launch_bounds__(256) void s_kernel(const float* __restrict__ a) {
    int row  = blockIdx.x * 8 + (threadIdx.x >> 5);
    int lane = threadIdx.x & 31;
    if (row >= N_NODES) return;
    float4 wh = *(const float4*)&g_Wh[(size_t)row * OUT_F + lane * 4];
    float4 a1 = *(const float4*)&a[lane * 4];
    float4 a2 = *(const float4*)&a[OUT_F + lane * 4];
    float p1 = wh.x * a1.x + wh.y * a1.y + wh.z * a1.z + wh.w * a1.w;
    float p2 = wh.x * a2.x + wh.y * a2.y + wh.z * a2.z + wh.w * a2.w;
    #pragma unroll
    for (int off = 16; off; off >>= 1) {
        p1 += __shfl_down_sync(0xFFFFFFFFu, p1, off);
        p2 += __shfl_down_sync(0xFFFFFFFFu, p2, off);
    }
    if (lane == 0) {
        g_s1[row] = p1;
        g_s2[row] = p2;
        g_segmax[row] = 0u;     // encodes below any real float
        g_denom[row]  = 0.0f;
    }
}

// ---------------- zero the output accumulator (d_out is poisoned) ------------
__global__ void zero_kernel(float4* __restrict__ out) {
    int idx = blockIdx.x * blockDim.x + threadIdx.x;
    if (idx < N_NODES * (OUT_F / 4))
        out[idx] = make_float4(0.f, 0.f, 0.f, 0.f);
}

// ---------------- edge pass 1: segment max -----------------------------------
__global__ __launch_bounds__(256) void edge_max_kernel(const void* __restrict__ ei) {
    int e = blockIdx.x * blockDim.x + threadIdx.x;
    if (e >= NUM_E) return;
    int s, d;
    load_edge(ei, e, s, d);
    float lg = leaky_logit(g_s1[s] + g_s2[d]);
    atomicMax(&g_segmax[s], enc_f(lg));
}

// ---------------- edge pass 2: exp-weight + scatter accumulate ---------------
__global__ __launch_bounds__(256) void edge_accum_kernel(const void* __restrict__ ei,
                                                         float* __restrict__ out) {
    int e = blockIdx.x * 8 + (threadIdx.x >> 5);   // warp per edge
    if (e >= NUM_E) return;
    int lane = threadIdx.x & 31;
    int s, d;
    load_edge(ei, e, s, d);                         // broadcast loads
    float lg = leaky_logit(g_s1[s] + g_s2[d]);
    float mx = dec_f(g_segmax[s]);
    float w  = __expf(lg - mx);
    if (lane == 0) atomicAdd(&g_denom[s], w);

    float4 wh = *(const float4*)&g_Wh[(size_t)d * OUT_F + lane * 4];
    float* dst = out + (size_t)s * OUT_F + lane * 4;
    asm volatile("red.global.add.v4.f32 [%0], {%1, %2, %3, %4};"
                 :: "l"(dst), "f"(wh.x * w), "f"(wh.y * w), "f"(wh.z * w), "f"(wh.w * w)
                 : "memory");
}

// ---------------- finalize: divide by denom + ReLU ----------------------------
__global__ void finalize_kernel(float* __restrict__ out) {
    int idx = blockIdx.x * blockDim.x + threadIdx.x;   // over float4s
    if (idx >= N_NODES * (OUT_F / 4)) return;
    int row = idx / (OUT_F / 4);
    float den = g_denom[row];
    float inv = (den > 0.0f) ? (1.0f / den) : 0.0f;
    float4 v = ((float4*)out)[idx];
    v.x = fmaxf(v.x * inv, 0.0f);
    v.y = fmaxf(v.y * inv, 0.0f);
    v.z = fmaxf(v.z * inv, 0.0f);
    v.w = fmaxf(v.w * inv, 0.0f);
    ((float4*)out)[idx] = v;
}

// ---------------- launch ------------------------------------------------------
extern "C" void kernel_launch(void* const* d_in, const int* in_sizes, int n_in,
                              void* d_out, int out_size) {
    const float* h  = (const float*)d_in[0];
    const float* W  = (const float*)d_in[1];
    const float* a  = (const float*)d_in[2];
    const void*  ei = d_in[3];
    float* out = (float*)d_out;

    detect_kernel<<<1, 256>>>((const int*)ei);
    gemm_kernel<<<(N_NODES + BM - 1) / BM, 256>>>(h, W);
    s_kernel<<<(N_NODES + 7) / 8, 256>>>(a);
    zero_kernel<<<(N_NODES * (OUT_F / 4) + 255) / 256, 256>>>((float4*)out);
    edge_max_kernel<<<(NUM_E + 255) / 256, 256>>>(ei);
    edge_accum_kernel<<<(NUM_E + 7) / 8, 256>>>(ei, out);
    finalize_kernel<<<(N_NODES * (OUT_F / 4) + 255) / 256, 256>>>(out);
}

// round 2
// speedup vs baseline: 1.9581x; 1.9581x over previous
#include <cuda_runtime.h>
#include <cstdint>

#define N_NODES 50000
#define NUM_E   1600000
#define IN_F    512
#define OUT_F   128
#define NEG_SLOPE 0.01f
#define INV_T     2.0f   // 1 / TEMPERATURE (0.5)

// ---------------- scratch (static device globals; no allocations) -----------
__device__ float    g_Wh[(size_t)N_NODES * OUT_F];   // 25.6 MB
__device__ float    g_s1[N_NODES];
__device__ float    g_s2[N_NODES];
__device__ int      g_cnt[N_NODES];                  // degree histogram
__device__ int      g_off[N_NODES + 1];              // CSR offsets
__device__ int      g_cursor[N_NODES];               // fill cursors
__device__ int      g_csr_dst[NUM_E];
__device__ float    g_csr_logit[NUM_E];
__device__ int      g_is64;

// ---------------- helpers ----------------------------------------------------
__device__ __forceinline__ float leaky_logit(float v) {
    v = (v >= 0.0f) ? v : NEG_SLOPE * v;
    return v * INV_T;
}

// ---------------- dtype detection for edge_index -----------------------------
// If the buffer is int64 (values < 50000, nonneg), every odd int32 word of the
// first 2048 is zero. For random int32 data this is astronomically unlikely.
__global__ void detect_kernel(const int* __restrict__ ei) {
    __shared__ int any;
    if (threadIdx.x == 0) any = 0;
    __syncthreads();
    for (int i = threadIdx.x; i < 2048; i += blockDim.x)
        if (ei[2 * i + 1] != 0) any = 1;
    __syncthreads();
    if (threadIdx.x == 0) g_is64 = any ? 0 : 1;
}

__global__ void init_cnt_kernel() {
    int i = blockIdx.x * blockDim.x + threadIdx.x;
    if (i < N_NODES) g_cnt[i] = 0;
}

__device__ __forceinline__ void load_edge(const void* ei, int e, int& s, int& d) {
    if (g_is64) {
        const long long* p = (const long long*)ei;
        s = (int)p[e];
        d = (int)p[NUM_E + e];
    } else {
        const int* p = (const int*)ei;
        s = p[e];
        d = p[NUM_E + e];
    }
}

// ---------------- GEMM: Wh = h @ W  (fp32 SIMT, BM=64 BN=128 BK=32) ----------
#define BM 64
#define BN 128
#define BK 32

__global__ __launch_bounds__(256) void gemm_kernel(const float* __restrict__ h,
                                                   const float* __restrict__ W) {
    __shared__ float As[BK][BM];   // transposed A tile
    __shared__ float Bs[BK][BN];

    const int block_row = blockIdx.x * BM;
    const int tid = threadIdx.x;
    const int tx  = tid & 31;   // col group (0..31) -> cols tx*4..tx*4+3
    const int ty  = tid >> 5;   // row group (0..7)  -> rows ty*8..ty*8+7

    float acc[8][4];
    #pragma unroll
    for (int i = 0; i < 8; i++)
        #pragma unroll
        for (int j = 0; j < 4; j++) acc[i][j] = 0.0f;

    for (int k0 = 0; k0 < IN_F; k0 += BK) {
        #pragma unroll
        for (int i = 0; i < 2; i++) {
            int t   = tid + i * 256;        // 0..511
            int row = t >> 3;               // 8 float4 per row
            int kc  = (t & 7) * 4;
            float4 v = make_float4(0.f, 0.f, 0.f, 0.f);
            int gr = block_row + row;
            if (gr < N_NODES)
                v = *(const float4*)&h[(size_t)gr * IN_F + k0 + kc];
            As[kc + 0][row] = v.x;
            As[kc + 1][row] = v.y;
            As[kc + 2][row] = v.z;
            As[kc + 3][row] = v.w;
        }
        #pragma unroll
        for (int i = 0; i < 4; i++) {
            int t   = tid + i * 256;        // 0..1023
            int row = t >> 5;               // 32 float4 per row
            int nc  = (t & 31) * 4;
            *(float4*)&Bs[row][nc] = *(const float4*)&W[(size_t)(k0 + row) * OUT_F + nc];
        }
        __syncthreads();

        #pragma unroll
        for (int k = 0; k < BK; k++) {
            float b[4];
            *(float4*)b = *(const float4*)&Bs[k][tx * 4];
            float a0[8];
            *(float4*)&a0[0] = *(const float4*)&As[k][ty * 8];
            *(float4*)&a0[4] = *(const float4*)&As[k][ty * 8 + 4];
            #pragma unroll
            for (int i = 0; i < 8; i++)
                #pragma unroll
                for (int j = 0; j < 4; j++)
                    acc[i][j] += a0[i] * b[j];
        }
        __syncthreads();
    }

    #pragma unroll
    for (int i = 0; i < 8; i++) {
        int gr = block_row + ty * 8 + i;
        if (gr < N_NODES)
            *(float4*)&g_Wh[(size_t)gr * OUT_F + tx * 4] = *(float4*)&acc[i][0];
    }
}

// ---------------- s1/s2 = Wh @ a1, Wh @ a2 -----------------------------------
__global__ __launch_bounds__(256) void s_kernel(const float* __restrict__ a) {
    int row  = blockIdx.x * 8 + (threadIdx.x >> 5);
    int lane = threadIdx.x & 31;
    if (row >= N_NODES) return;
    float4 wh = *(const float4*)&g_Wh[(size_t)row * OUT_F + lane * 4];
    float4 a1 = *(const float4*)&a[lane * 4];
    float4 a2 = *(const float4*)&a[OUT_F + lane * 4];
    float p1 = wh.x * a1.x + wh.y * a1.y + wh.z * a1.z + wh.w * a1.w;
    float p2 = wh.x * a2.x + wh.y * a2.y + wh.z * a2.z + wh.w * a2.w;
    #pragma unroll
    for (int off = 16; off; off >>= 1) {
        p1 += __shfl_down_sync(0xFFFFFFFFu, p1, off);
        p2 += __shfl_down_sync(0xFFFFFFFFu, p2, off);
    }
    if (lane == 0) {
        g_s1[row] = p1;
        g_s2[row] = p2;
    }
}

// ---------------- CSR build: histogram ----------------------------------------
__global__ __launch_bounds__(256) void hist_kernel(const void* __restrict__ ei) {
    int e = blockIdx.x * blockDim.x + threadIdx.x;
    if (e >= NUM_E) return;
    int s, d;
    load_edge(ei, e, s, d);
    atomicAdd(&g_cnt[s], 1);
}

// ---------------- CSR build: exclusive scan (single block) --------------------
__global__ __launch_bounds__(1024) void scan_kernel() {
    __shared__ int warpsum[32];
    __shared__ int carry_sm;
    const int tid  = threadIdx.x;
    const int lane = tid & 31;
    const int wid  = tid >> 5;
    if (tid == 0) carry_sm = 0;
    __syncthreads();

    for (int chunk = 0; chunk < N_NODES; chunk += 1024) {
        int i = chunk + tid;
        int v = (i < N_NODES) ? g_cnt[i] : 0;
        // warp inclusive scan
        int x = v;
        #pragma unroll
        for (int o = 1; o < 32; o <<= 1) {
            int y = __shfl_up_sync(0xFFFFFFFFu, x, o);
            if (lane >= o) x += y;
        }
        if (lane == 31) warpsum[wid] = x;
        __syncthreads();
        if (wid == 0) {
            int s = warpsum[lane];
            #pragma unroll
            for (int o = 1; o < 32; o <<= 1) {
                int y = __shfl_up_sync(0xFFFFFFFFu, s, o);
                if (lane >= o) s += y;
            }
            warpsum[lane] = s;
        }
        __syncthreads();
        int base  = (wid > 0) ? warpsum[wid - 1] : 0;
        int carry = carry_sm;
        int excl  = carry + base + x - v;
        if (i < N_NODES) {
            g_off[i]    = excl;
            g_cursor[i] = excl;
        }
        __syncthreads();
        if (tid == 0) carry_sm = carry + warpsum[31];
        __syncthreads();
    }
    if (tid == 0) g_off[N_NODES] = carry_sm;   // == NUM_E
}

// ---------------- CSR build: fill (dst, logit) --------------------------------
__global__ __launch_bounds__(256) void fill_kernel(const void* __restrict__ ei) {
    int e = blockIdx.x * blockDim.x + threadIdx.x;
    if (e >= NUM_E) return;
    int s, d;
    load_edge(ei, e, s, d);
    float lg  = leaky_logit(__ldg(&g_s1[s]) + __ldg(&g_s2[d]));
    int   pos = atomicAdd(&g_cursor[s], 1);
    g_csr_dst[pos]   = d;
    g_csr_logit[pos] = lg;
}

// ---------------- aggregate: warp per src node --------------------------------
// max -> exp weights -> denom -> sum w*Wh[dst] -> relu(acc/denom) -> out row
__global__ __launch_bounds__(256) void agg_kernel(float* __restrict__ out) {
    int src  = blockIdx.x * 8 + (threadIdx.x >> 5);
    if (src >= N_NODES) return;
    int lane = threadIdx.x & 31;
    int beg  = g_off[src];
    int end  = g_off[src + 1];

    float4* out4 = (float4*)out;
    if (beg == end) {
        out4[(size_t)src * 32 + lane] = make_float4(0.f, 0.f, 0.f, 0.f);
        return;
    }

    // segment max over this node's logits
    float m = -3.0e38f;
    for (int i = beg + lane; i < end; i += 32)
        m = fmaxf(m, g_csr_logit[i]);
    #pragma unroll
    for (int o = 16; o; o >>= 1)
        m = fmaxf(m, __shfl_xor_sync(0xFFFFFFFFu, m, o));

    const float4* Wh4 = (const float4*)g_Wh;
    float ax = 0.f, ay = 0.f, az = 0.f, aw = 0.f;
    float den = 0.f;

    for (int base = beg; base < end; base += 32) {
        int  idx   = base + lane;
        bool valid = idx < end;
        int   dn = valid ? g_csr_dst[idx] : 0;
        float w  = valid ? __expf(g_csr_logit[idx] - m) : 0.0f;
        den += w;
        int cnt = end - base;
        if (cnt >= 32) {
            #pragma unroll 8
            for (int j = 0; j < 32; j++) {
                int   dj = __shfl_sync(0xFFFFFFFFu, dn, j);
                float wj = __shfl_sync(0xFFFFFFFFu, w,  j);
                float4 v = Wh4[(size_t)dj * 32 + lane];
                ax += wj * v.x; ay += wj * v.y; az += wj * v.z; aw += wj * v.w;
            }
        } else {
            for (int j = 0; j < cnt; j++) {
                int   dj = __shfl_sync(0xFFFFFFFFu, dn, j);
                float wj = __shfl_sync(0xFFFFFFFFu, w,  j);
                float4 v = Wh4[(size_t)dj * 32 + lane];
                ax += wj * v.x; ay += wj * v.y; az += wj * v.z; aw += wj * v.w;
            }
        }
    }
    #pragma unroll
    for (int o = 16; o; o >>= 1)
        den += __shfl_xor_sync(0xFFFFFFFFu, den, o);
    float inv = (den > 0.0f) ? (1.0f / den) : 0.0f;

    float4 r;
    r.x = fmaxf(ax * inv, 0.0f);
    r.y = fmaxf(ay * inv, 0.0f);
    r.z = fmaxf(az * inv, 0.0f);
    r.w = fmaxf(aw * inv, 0.0f);
    out4[(size_t)src * 32 + lane] = r;
}

// ---------------- launch ------------------------------------------------------
extern "C" void kernel_launch(void* const* d_in, const int* in_sizes, int n_in,
                              void* d_out, int out_size) {
    const float* h  = (const float*)d_in[0];
    const float* W  = (const float*)d_in[1];
    const float* a  = (const float*)d_in[2];
    const void*  ei = d_in[3];
    float* out = (float*)d_out;

    detect_kernel<<<1, 256>>>((const int*)ei);
    init_cnt_kernel<<<(N_NODES + 255) / 256, 256>>>();
    gemm_kernel<<<(N_NODES + BM - 1) / BM, 256>>>(h, W);
    s_kernel<<<(N_NODES + 7) / 8, 256>>>(a);
    hist_kernel<<<(NUM_E + 255) / 256, 256>>>(ei);
    scan_kernel<<<1, 1024>>>();
    fill_kernel<<<(NUM_E + 255) / 256, 256>>>(ei);
    agg_kernel<<<(N_NODES + 7) / 8, 256>>>(out);
}

// round 4
// speedup vs baseline: 2.5931x; 1.3243x over previous
#include <cuda_runtime.h>
#include <cuda_bf16.h>
#include <cstdint>

#define N_NODES 50000
#define NUM_E   1600000
#define IN_F    512
#define OUT_F   128
#define NEG_SLOPE 0.01f
#define INV_T     2.0f   // 1 / TEMPERATURE (0.5)

#define TILE_M   128
#define N_TILES  391                   // ceil(50000/128)
#define PAD_ROWS (N_TILES * TILE_M)    // 50048
#define GBK      64                    // K per pipeline buffer (bf16 elems)
#define NBUF     24                    // 3 passes x 8 k-chunks
#define STAGE_BYTES 32768              // A tile 16K + B tile 16K
#define GEMM_SMEM   (2 * STAGE_BYTES)  // 64 KB double buffer

// ---------------- scratch (static device globals; no allocations) -----------
__device__ float    g_Wh[(size_t)N_NODES * OUT_F];      // 25.6 MB
__device__ __nv_bfloat16 g_Ah[(size_t)PAD_ROWS * IN_F]; // 51.2 MB
__device__ __nv_bfloat16 g_Al[(size_t)PAD_ROWS * IN_F]; // 51.2 MB
__device__ __nv_bfloat16 g_Bh[(size_t)OUT_F * IN_F];    // 128 KB  (B^T: [n][k])
__device__ __nv_bfloat16 g_Bl[(size_t)OUT_F * IN_F];    // 128 KB
__device__ float    g_s1[N_NODES];
__device__ float    g_s2[N_NODES];
__device__ int      g_cnt[N_NODES];
__device__ int      g_off[N_NODES + 1];
__device__ int      g_cursor[N_NODES];
__device__ int      g_csr_dst[NUM_E];
__device__ float    g_csr_logit[NUM_E];
__device__ int      g_is64;

// ---------------- helpers ----------------------------------------------------
__device__ __forceinline__ uint32_t smem_u32(const void* p) {
    uint32_t a;
    asm("{ .reg .u64 t; cvta.to.shared.u64 t, %1; cvt.u32.u64 %0, t; }" : "=r"(a) : "l"(p));
    return a;
}
__device__ __forceinline__ void cp_async16(uint32_t dst, const void* src) {
    asm volatile("cp.async.cg.shared.global [%0], [%1], 16;"
                 :: "r"(dst), "l"(__cvta_generic_to_global(src)) : "memory");
}
#define CP_COMMIT() asm volatile("cp.async.commit_group;" ::: "memory")
#define CP_WAIT1()  asm volatile("cp.async.wait_group 1;" ::: "memory")

__device__ __forceinline__ void ldsm_x4(uint32_t* r, uint32_t addr) {
    asm volatile("ldmatrix.sync.aligned.m8n8.x4.shared.b16 {%0,%1,%2,%3}, [%4];"
                 : "=r"(r[0]), "=r"(r[1]), "=r"(r[2]), "=r"(r[3]) : "r"(addr));
}
__device__ __forceinline__ void mma_bf16(float* d, const uint32_t* a, const uint32_t* b) {
    asm volatile("mma.sync.aligned.m16n8k16.row.col.f32.bf16.bf16.f32 "
                 "{%0,%1,%2,%3}, {%4,%5,%6,%7}, {%8,%9}, {%0,%1,%2,%3};"
                 : "+f"(d[0]), "+f"(d[1]), "+f"(d[2]), "+f"(d[3])
                 : "r"(a[0]), "r"(a[1]), "r"(a[2]), "r"(a[3]), "r"(b[0]), "r"(b[1]));
}

__device__ __forceinline__ float leaky_logit(float v) {
    v = (v >= 0.0f) ? v : NEG_SLOPE * v;
    return v * INV_T;
}

// ---------------- split-bf16 conversion --------------------------------------
__device__ __forceinline__ void split8(const float* v, unsigned short* hb, unsigned short* lb) {
    #pragma unroll
    for (int j = 0; j < 8; j++) {
        __nv_bfloat16 hv = __float2bfloat16(v[j]);
        float hf = __bfloat162float(hv);
        __nv_bfloat16 lv = __float2bfloat16(v[j] - hf);
        hb[j] = __bfloat16_as_ushort(hv);
        lb[j] = __bfloat16_as_ushort(lv);
    }
}
__device__ __forceinline__ uint4 pack8(const unsigned short* b) {
    uint4 q;
    q.x = (uint32_t)b[0] | ((uint32_t)b[1] << 16);
    q.y = (uint32_t)b[2] | ((uint32_t)b[3] << 16);
    q.z = (uint32_t)b[4] | ((uint32_t)b[5] << 16);
    q.w = (uint32_t)b[6] | ((uint32_t)b[7] << 16);
    return q;
}

// h[r, k] -> Ah/Al bf16 row-major, zero-padded to PAD_ROWS
__global__ __launch_bounds__(256) void convert_h_kernel(const float* __restrict__ h) {
    int idx = blockIdx.x * 256 + threadIdx.x;           // one per 8 elems
    if (idx >= PAD_ROWS * (IN_F / 8)) return;
    int r  = idx / (IN_F / 8);
    int c8 = idx % (IN_F / 8);
    float v[8];
    if (r < N_NODES) {
        const float4* p = (const float4*)&h[(size_t)r * IN_F + c8 * 8];
        float4 x = p[0], y = p[1];
        v[0] = x.x; v[1] = x.y; v[2] = x.z; v[3] = x.w;
        v[4] = y.x; v[5] = y.y; v[6] = y.z; v[7] = y.w;
    } else {
        #pragma unroll
        for (int j = 0; j < 8; j++) v[j] = 0.0f;
    }
    unsigned short hb[8], lb[8];
    split8(v, hb, lb);
    size_t off = (size_t)r * IN_F + c8 * 8;
    *(uint4*)&g_Ah[off] = pack8(hb);
    *(uint4*)&g_Al[off] = pack8(lb);
}

// W[k, n] -> B^T[n][k] bf16 (hi/lo)
__global__ __launch_bounds__(256) void convert_w_kernel(const float* __restrict__ W) {
    int idx = blockIdx.x * 256 + threadIdx.x;
    if (idx >= OUT_F * (IN_F / 8)) return;
    int n  = idx / (IN_F / 8);
    int k8 = (idx % (IN_F / 8)) * 8;
    float v[8];
    #pragma unroll
    for (int j = 0; j < 8; j++)
        v[j] = W[(size_t)(k8 + j) * OUT_F + n];
    unsigned short hb[8], lb[8];
    split8(v, hb, lb);
    size_t off = (size_t)n * IN_F + k8;
    *(uint4*)&g_Bh[off] = pack8(hb);
    *(uint4*)&g_Bl[off] = pack8(lb);
}

// ---------------- GEMM: Wh = h @ W  (mma.sync bf16 x3, fp32 accum) -----------
// CTA 128x128, BK=64, double-buffered cp.async, SW-swizzled smem rows (128B).
__global__ __launch_bounds__(256, 2) void gemm_mma_kernel() {
    extern __shared__ char smx[];
    const int tid  = threadIdx.x;
    const int lane = tid & 31, wid = tid >> 5;
    const int warp_m = wid & 3, warp_n = wid >> 2;   // 4 x 2 warp grid
    const int tileRow = blockIdx.x * TILE_M;
    const uint32_t sbase = smem_u32(smx);

    float acc[2][8][4];
    #pragma unroll
    for (int mt = 0; mt < 2; mt++)
        #pragma unroll
        for (int nt = 0; nt < 8; nt++)
            #pragma unroll
            for (int q = 0; q < 4; q++) acc[mt][nt][q] = 0.0f;

    // ---- stage loader: A tile 128x64 bf16 (16KB) + B tile 128x64 (16KB) ----
    auto load_stage = [&](int stage, int it) {
        int p = it >> 3, kIdx = it & 7;
        const __nv_bfloat16* Asrc = (p == 2) ? g_Al : g_Ah;
        const __nv_bfloat16* Bsrc = (p == 1) ? g_Bl : g_Bh;
        int k0 = kIdx * GBK;
        uint32_t sA = sbase + stage * STAGE_BYTES;
        uint32_t sB = sA + 16384;
        #pragma unroll
        for (int i = 0; i < 4; i++) {
            int cid = tid + i * 256;            // 0..1023
            int row = cid >> 3, c = cid & 7;    // 8 x 16B chunks per row
            uint32_t dst = sA + row * 128 + ((c ^ (row & 7)) << 4);
            cp_async16(dst, Asrc + (size_t)(tileRow + row) * IN_F + k0 + c * 8);
        }
        #pragma unroll
        for (int i = 0; i < 4; i++) {
            int cid = tid + i * 256;
            int row = cid >> 3, c = cid & 7;
            uint32_t dst = sB + row * 128 + ((c ^ (row & 7)) << 4);
            cp_async16(dst, Bsrc + (size_t)row * IN_F + k0 + c * 8);
        }
    };

    load_stage(0, 0);
    CP_COMMIT();

    const int mi = lane >> 3, r8 = lane & 7;    // ldmatrix lane decomposition

    for (int it = 0; it < NBUF; it++) {
        if (it + 1 < NBUF) load_stage((it + 1) & 1, it + 1);
        CP_COMMIT();
        CP_WAIT1();
        __syncthreads();

        uint32_t sA = sbase + (it & 1) * STAGE_BYTES;
        uint32_t sB = sA + 16384;

        #pragma unroll
        for (int ks = 0; ks < 4; ks++) {        // 4 k16-steps per buffer
            uint32_t a[2][4];
            #pragma unroll
            for (int mt = 0; mt < 2; mt++) {
                int arow = warp_m * 32 + mt * 16 + r8 + (mi & 1) * 8;
                int ac   = ks * 2 + (mi >> 1);
                ldsm_x4(a[mt], sA + arow * 128 + ((ac ^ (arow & 7)) << 4));
            }
            uint32_t b[8][2];
            #pragma unroll
            for (int np = 0; np < 4; np++) {    // pairs of n-tiles
                int brow = warp_n * 64 + np * 16 + (mi >> 1) * 8 + r8;
                int bc   = ks * 2 + (mi & 1);
                uint32_t r[4];
                ldsm_x4(r, sB + brow * 128 + ((bc ^ (brow & 7)) << 4));
                b[np * 2][0]     = r[0]; b[np * 2][1]     = r[1];
                b[np * 2 + 1][0] = r[2]; b[np * 2 + 1][1] = r[3];
            }
            #pragma unroll
            for (int mt = 0; mt < 2; mt++)
                #pragma unroll
                for (int nt = 0; nt < 8; nt++)
                    mma_bf16(acc[mt][nt], a[mt], b[nt]);
        }
        __syncthreads();
    }

    // ---- epilogue: write fp32 rows of g_Wh ----
    int row0 = tileRow + warp_m * 32 + (lane >> 2);
    int col0 = warp_n * 64 + (lane & 3) * 2;
    #pragma unroll
    for (int mt = 0; mt < 2; mt++) {
        int r = row0 + mt * 16;
        #pragma unroll
        for (int nt = 0; nt < 8; nt++) {
            int c = col0 + nt * 8;
            if (r < N_NODES)
                *(float2*)&g_Wh[(size_t)r * OUT_F + c] =
                    make_float2(acc[mt][nt][0], acc[mt][nt][1]);
            if (r + 8 < N_NODES)
                *(float2*)&g_Wh[(size_t)(r + 8) * OUT_F + c] =
                    make_float2(acc[mt][nt][2], acc[mt][nt][3]);
        }
    }
}

// ---------------- dtype detection for edge_index -----------------------------
__global__ void detect_kernel(const int* __restrict__ ei) {
    __shared__ int any;
    if (threadIdx.x == 0) any = 0;
    __syncthreads();
    for (int i = threadIdx.x; i < 2048; i += blockDim.x)
        if (ei[2 * i + 1] != 0) any = 1;
    __syncthreads();
    if (threadIdx.x == 0) g_is64 = any ? 0 : 1;
}

__global__ void init_cnt_kernel() {
    int i = blockIdx.x * blockDim.x + threadIdx.x;
    if (i < N_NODES) g_cnt[i] = 0;
}

__device__ __forceinline__ void load_edge(const void* ei, int e, int& s, int& d) {
    if (g_is64) {
        const long long* p = (const long long*)ei;
        s = (int)p[e];
        d = (int)p[NUM_E + e];
    } else {
        const int* p = (const int*)ei;
        s = p[e];
        d = p[NUM_E + e];
    }
}

// ---------------- s1/s2 = Wh @ a1, Wh @ a2 -----------------------------------
__global__ __launch_bounds__(256) void s_kernel(const float* __restrict__ a) {
    int row  = blockIdx.x * 8 + (threadIdx.x >> 5);
    int lane = threadIdx.x & 31;
    if (row >= N_NODES) return;
    float4 wh = *(const float4*)&g_Wh[(size_t)row * OUT_F + lane * 4];
    float4 a1 = *(const float4*)&a[lane * 4];
    float4 a2 = *(const float4*)&a[OUT_F + lane * 4];
    float p1 = wh.x * a1.x + wh.y * a1.y + wh.z * a1.z + wh.w * a1.w;
    float p2 = wh.x * a2.x + wh.y * a2.y + wh.z * a2.z + wh.w * a2.w;
    #pragma unroll
    for (int off = 16; off; off >>= 1) {
        p1 += __shfl_down_sync(0xFFFFFFFFu, p1, off);
        p2 += __shfl_down_sync(0xFFFFFFFFu, p2, off);
    }
    if (lane == 0) {
        g_s1[row] = p1;
        g_s2[row] = p2;
    }
}

// ---------------- CSR build ----------------------------------------------------
__global__ __launch_bounds__(256) void hist_kernel(const void* __restrict__ ei) {
    int e = blockIdx.x * blockDim.x + threadIdx.x;
    if (e >= NUM_E) return;
    int s, d;
    load_edge(ei, e, s, d);
    atomicAdd(&g_cnt[s], 1);
}

__global__ __launch_bounds__(1024) void scan_kernel() {
    __shared__ int warpsum[32];
    __shared__ int carry_sm;
    const int tid  = threadIdx.x;
    const int lane = tid & 31;
    const int wid  = tid >> 5;
    if (tid == 0) carry_sm = 0;
    __syncthreads();

    for (int chunk = 0; chunk < N_NODES; chunk += 1024) {
        int i = chunk + tid;
        int v = (i < N_NODES) ? g_cnt[i] : 0;
        int x = v;
        #pragma unroll
        for (int o = 1; o < 32; o <<= 1) {
            int y = __shfl_up_sync(0xFFFFFFFFu, x, o);
            if (lane >= o) x += y;
        }
        if (lane == 31) warpsum[wid] = x;
        __syncthreads();
        if (wid == 0) {
            int s = warpsum[lane];
            #pragma unroll
            for (int o = 1; o < 32; o <<= 1) {
                int y = __shfl_up_sync(0xFFFFFFFFu, s, o);
                if (lane >= o) s += y;
            }
            warpsum[lane] = s;
        }
        __syncthreads();
        int base  = (wid > 0) ? warpsum[wid - 1] : 0;
        int carry = carry_sm;
        int excl  = carry + base + x - v;
        if (i < N_NODES) {
            g_off[i]    = excl;
            g_cursor[i] = excl;
        }
        __syncthreads();
        if (tid == 0) carry_sm = carry + warpsum[31];
        __syncthreads();
    }
    if (tid == 0) g_off[N_NODES] = carry_sm;
}

__global__ __launch_bounds__(256) void fill_kernel(const void* __restrict__ ei) {
    int e = blockIdx.x * blockDim.x + threadIdx.x;
    if (e >= NUM_E) return;
    int s, d;
    load_edge(ei, e, s, d);
    float lg  = leaky_logit(__ldg(&g_s1[s]) + __ldg(&g_s2[d]));
    int   pos = atomicAdd(&g_cursor[s], 1);
    g_csr_dst[pos]   = d;
    g_csr_logit[pos] = lg;
}

// ---------------- aggregate: warp per src node --------------------------------
__global__ __launch_bounds__(256) void agg_kernel(float* __restrict__ out) {
    int src  = blockIdx.x * 8 + (threadIdx.x >> 5);
    if (src >= N_NODES) return;
    int lane = threadIdx.x & 31;
    int beg  = g_off[src];
    int end  = g_off[src + 1];

    float4* out4 = (float4*)out;
    if (beg == end) {
        out4[(size_t)src * 32 + lane] = make_float4(0.f, 0.f, 0.f, 0.f);
        return;
    }

    float m = -3.0e38f;
    for (int i = beg + lane; i < end; i += 32)
        m = fmaxf(m, g_csr_logit[i]);
    #pragma unroll
    for (int o = 16; o; o >>= 1)
        m = fmaxf(m, __shfl_xor_sync(0xFFFFFFFFu, m, o));

    const float4* Wh4 = (const float4*)g_Wh;
    float ax = 0.f, ay = 0.f, az = 0.f, aw = 0.f;
    float den = 0.f;

    for (int base = beg; base < end; base += 32) {
        int  idx   = base + lane;
        bool valid = idx < end;
        int   dn = valid ? g_csr_dst[idx] : 0;
        float w  = valid ? __expf(g_csr_logit[idx] - m) : 0.0f;
        den += w;
        int cnt = end - base;
        if (cnt >= 32) {
            #pragma unroll 8
            for (int j = 0; j < 32; j++) {
                int   dj = __shfl_sync(0xFFFFFFFFu, dn, j);
                float wj = __shfl_sync(0xFFFFFFFFu, w,  j);
                float4 v = Wh4[(size_t)dj * 32 + lane];
                ax += wj * v.x; ay += wj * v.y; az += wj * v.z; aw += wj * v.w;
            }
        } else {
            for (int j = 0; j < cnt; j++) {
                int   dj = __shfl_sync(0xFFFFFFFFu, dn, j);
                float wj = __shfl_sync(0xFFFFFFFFu, w,  j);
                float4 v = Wh4[(size_t)dj * 32 + lane];
                ax += wj * v.x; ay += wj * v.y; az += wj * v.z; aw += wj * v.w;
            }
        }
    }
    #pragma unroll
    for (int o = 16; o; o >>= 1)
        den += __shfl_xor_sync(0xFFFFFFFFu, den, o);
    float inv = (den > 0.0f) ? (1.0f / den) : 0.0f;

    float4 r;
    r.x = fmaxf(ax * inv, 0.0f);
    r.y = fmaxf(ay * inv, 0.0f);
    r.z = fmaxf(az * inv, 0.0f);
    r.w = fmaxf(aw * inv, 0.0f);
    out4[(size_t)src * 32 + lane] = r;
}

// ---------------- launch ------------------------------------------------------
extern "C" void kernel_launch(void* const* d_in, const int* in_sizes, int n_in,
                              void* d_out, int out_size) {
    const float* h  = (const float*)d_in[0];
    const float* W  = (const float*)d_in[1];
    const float* a  = (const float*)d_in[2];
    const void*  ei = d_in[3];
    float* out = (float*)d_out;

    cudaFuncSetAttribute(gemm_mma_kernel,
                         cudaFuncAttributeMaxDynamicSharedMemorySize, GEMM_SMEM);

    detect_kernel<<<1, 256>>>((const int*)ei);
    init_cnt_kernel<<<(N_NODES + 255) / 256, 256>>>();
    convert_h_kernel<<<(PAD_ROWS * (IN_F / 8) + 255) / 256, 256>>>(h);
    convert_w_kernel<<<(OUT_F * (IN_F / 8) + 255) / 256, 256>>>(W);
    gemm_mma_kernel<<<N_TILES, 256, GEMM_SMEM>>>();
    s_kernel<<<(N_NODES + 7) / 8, 256>>>(a);
    hist_kernel<<<(NUM_E + 255) / 256, 256>>>(ei);
    scan_kernel<<<1, 1024>>>();
    fill_kernel<<<(NUM_E + 255) / 256, 256>>>(ei);
    agg_kernel<<<(N_NODES + 7) / 8, 256>>>(out);
}

// round 5
// speedup vs baseline: 3.1444x; 1.2126x over previous
#include <cuda_runtime.h>
#include <cuda_bf16.h>
#include <cstdint>

#define N_NODES 50000
#define NUM_E   1600000
#define IN_F    512
#define OUT_F   128
#define NEG_SLOPE 0.01f
#define INV_T     2.0f   // 1 / TEMPERATURE (0.5)

#define TILE_M   128
#define N_TILES  391                   // ceil(50000/128)
#define PAD_ROWS (N_TILES * TILE_M)    // 50048
#define GBK      64                    // K per pipeline buffer (bf16 elems)
#define NBUF     24                    // 3 passes x 8 k-chunks
#define STAGE_BYTES 32768              // A tile 16K + B tile 16K
#define GEMM_SMEM   (2 * STAGE_BYTES)  // 64 KB double buffer

// ---------------- scratch (static device globals; no allocations) -----------
__device__ float    g_Wh[(size_t)N_NODES * OUT_F];      // 25.6 MB
__device__ __nv_bfloat16 g_Ah[(size_t)PAD_ROWS * IN_F]; // 51.2 MB
__device__ __nv_bfloat16 g_Al[(size_t)PAD_ROWS * IN_F]; // 51.2 MB
__device__ __nv_bfloat16 g_Bh[(size_t)OUT_F * IN_F];    // 128 KB  (B^T: [n][k])
__device__ __nv_bfloat16 g_Bl[(size_t)OUT_F * IN_F];    // 128 KB
__device__ float    g_s1[N_NODES];
__device__ float    g_s2[N_NODES];
__device__ int      g_cnt[N_NODES];
__device__ int      g_off[N_NODES + 1];
__device__ int      g_cursor[N_NODES];
__device__ int      g_csr_dst[NUM_E];
__device__ float    g_csr_logit[NUM_E];
__device__ int      g_is64;

// ---------------- helpers ----------------------------------------------------
__device__ __forceinline__ uint32_t smem_u32(const void* p) {
    uint32_t a;
    asm("{ .reg .u64 t; cvta.to.shared.u64 t, %1; cvt.u32.u64 %0, t; }" : "=r"(a) : "l"(p));
    return a;
}
__device__ __forceinline__ void cp_async16(uint32_t dst, const void* src) {
    asm volatile("cp.async.cg.shared.global [%0], [%1], 16;"
                 :: "r"(dst), "l"(__cvta_generic_to_global(src)) : "memory");
}
#define CP_COMMIT() asm volatile("cp.async.commit_group;" ::: "memory")
#define CP_WAIT1()  asm volatile("cp.async.wait_group 1;" ::: "memory")

__device__ __forceinline__ void ldsm_x4(uint32_t* r, uint32_t addr) {
    asm volatile("ldmatrix.sync.aligned.m8n8.x4.shared.b16 {%0,%1,%2,%3}, [%4];"
                 : "=r"(r[0]), "=r"(r[1]), "=r"(r[2]), "=r"(r[3]) : "r"(addr));
}
__device__ __forceinline__ void mma_bf16(float* d, const uint32_t* a, const uint32_t* b) {
    asm volatile("mma.sync.aligned.m16n8k16.row.col.f32.bf16.bf16.f32 "
                 "{%0,%1,%2,%3}, {%4,%5,%6,%7}, {%8,%9}, {%0,%1,%2,%3};"
                 : "+f"(d[0]), "+f"(d[1]), "+f"(d[2]), "+f"(d[3])
                 : "r"(a[0]), "r"(a[1]), "r"(a[2]), "r"(a[3]), "r"(b[0]), "r"(b[1]));
}

__device__ __forceinline__ float leaky_logit(float v) {
    v = (v >= 0.0f) ? v : NEG_SLOPE * v;
    return v * INV_T;
}

// ---------------- split-bf16 conversion --------------------------------------
__device__ __forceinline__ void split8(const float* v, unsigned short* hb, unsigned short* lb) {
    #pragma unroll
    for (int j = 0; j < 8; j++) {
        __nv_bfloat16 hv = __float2bfloat16(v[j]);
        float hf = __bfloat162float(hv);
        __nv_bfloat16 lv = __float2bfloat16(v[j] - hf);
        hb[j] = __bfloat16_as_ushort(hv);
        lb[j] = __bfloat16_as_ushort(lv);
    }
}
__device__ __forceinline__ uint4 pack8(const unsigned short* b) {
    uint4 q;
    q.x = (uint32_t)b[0] | ((uint32_t)b[1] << 16);
    q.y = (uint32_t)b[2] | ((uint32_t)b[3] << 16);
    q.z = (uint32_t)b[4] | ((uint32_t)b[5] << 16);
    q.w = (uint32_t)b[6] | ((uint32_t)b[7] << 16);
    return q;
}

// h[r, k] -> Ah/Al bf16 row-major, zero-padded; also zeroes g_s1/g_s2
__global__ __launch_bounds__(256) void convert_h_kernel(const float* __restrict__ h) {
    int idx = blockIdx.x * 256 + threadIdx.x;           // one per 8 elems
    if (idx < N_NODES) { g_s1[idx] = 0.0f; g_s2[idx] = 0.0f; }
    if (idx >= PAD_ROWS * (IN_F / 8)) return;
    int r  = idx / (IN_F / 8);
    int c8 = idx % (IN_F / 8);
    float v[8];
    if (r < N_NODES) {
        const float4* p = (const float4*)&h[(size_t)r * IN_F + c8 * 8];
        float4 x = p[0], y = p[1];
        v[0] = x.x; v[1] = x.y; v[2] = x.z; v[3] = x.w;
        v[4] = y.x; v[5] = y.y; v[6] = y.z; v[7] = y.w;
    } else {
        #pragma unroll
        for (int j = 0; j < 8; j++) v[j] = 0.0f;
    }
    unsigned short hb[8], lb[8];
    split8(v, hb, lb);
    size_t off = (size_t)r * IN_F + c8 * 8;
    *(uint4*)&g_Ah[off] = pack8(hb);
    *(uint4*)&g_Al[off] = pack8(lb);
}

// W[k, n] -> B^T[n][k] bf16 (hi/lo)
__global__ __launch_bounds__(256) void convert_w_kernel(const float* __restrict__ W) {
    int idx = blockIdx.x * 256 + threadIdx.x;
    if (idx >= OUT_F * (IN_F / 8)) return;
    int n  = idx / (IN_F / 8);
    int k8 = (idx % (IN_F / 8)) * 8;
    float v[8];
    #pragma unroll
    for (int j = 0; j < 8; j++)
        v[j] = W[(size_t)(k8 + j) * OUT_F + n];
    unsigned short hb[8], lb[8];
    split8(v, hb, lb);
    size_t off = (size_t)n * IN_F + k8;
    *(uint4*)&g_Bh[off] = pack8(hb);
    *(uint4*)&g_Bl[off] = pack8(lb);
}

// ---------------- GEMM: Wh = h @ W  (mma.sync bf16 x3, fp32 accum) -----------
// CTA 128x128, BK=64, double-buffered cp.async, SW-swizzled smem rows (128B).
// Epilogue also computes s1 = Wh@a1, s2 = Wh@a2 (fused; atomicAdd partials).
__global__ __launch_bounds__(256, 2) void gemm_mma_kernel(const float* __restrict__ ga) {
    extern __shared__ char smx[];
    const int tid  = threadIdx.x;
    const int lane = tid & 31, wid = tid >> 5;
    const int warp_m = wid & 3, warp_n = wid >> 2;   // 4 x 2 warp grid
    const int tileRow = blockIdx.x * TILE_M;
    const uint32_t sbase = smem_u32(smx);

    float acc[2][8][4];
    #pragma unroll
    for (int mt = 0; mt < 2; mt++)
        #pragma unroll
        for (int nt = 0; nt < 8; nt++)
            #pragma unroll
            for (int q = 0; q < 4; q++) acc[mt][nt][q] = 0.0f;

    auto load_stage = [&](int stage, int it) {
        int p = it >> 3, kIdx = it & 7;
        const __nv_bfloat16* Asrc = (p == 2) ? g_Al : g_Ah;
        const __nv_bfloat16* Bsrc = (p == 1) ? g_Bl : g_Bh;
        int k0 = kIdx * GBK;
        uint32_t sA = sbase + stage * STAGE_BYTES;
        uint32_t sB = sA + 16384;
        #pragma unroll
        for (int i = 0; i < 4; i++) {
            int cid = tid + i * 256;            // 0..1023
            int row = cid >> 3, c = cid & 7;    // 8 x 16B chunks per row
            uint32_t dst = sA + row * 128 + ((c ^ (row & 7)) << 4);
            cp_async16(dst, Asrc + (size_t)(tileRow + row) * IN_F + k0 + c * 8);
        }
        #pragma unroll
        for (int i = 0; i < 4; i++) {
            int cid = tid + i * 256;
            int row = cid >> 3, c = cid & 7;
            uint32_t dst = sB + row * 128 + ((c ^ (row & 7)) << 4);
            cp_async16(dst, Bsrc + (size_t)row * IN_F + k0 + c * 8);
        }
    };

    load_stage(0, 0);
    CP_COMMIT();

    const int mi = lane >> 3, r8 = lane & 7;    // ldmatrix lane decomposition

    for (int it = 0; it < NBUF; it++) {
        if (it + 1 < NBUF) load_stage((it + 1) & 1, it + 1);
        CP_COMMIT();
        CP_WAIT1();
        __syncthreads();

        uint32_t sA = sbase + (it & 1) * STAGE_BYTES;
        uint32_t sB = sA + 16384;

        #pragma unroll
        for (int ks = 0; ks < 4; ks++) {        // 4 k16-steps per buffer
            uint32_t a[2][4];
            #pragma unroll
            for (int mt = 0; mt < 2; mt++) {
                int arow = warp_m * 32 + mt * 16 + r8 + (mi & 1) * 8;
                int ac   = ks * 2 + (mi >> 1);
                ldsm_x4(a[mt], sA + arow * 128 + ((ac ^ (arow & 7)) << 4));
            }
            uint32_t b[8][2];
            #pragma unroll
            for (int np = 0; np < 4; np++) {    // pairs of n-tiles
                int brow = warp_n * 64 + np * 16 + (mi >> 1) * 8 + r8;
                int bc   = ks * 2 + (mi & 1);
                uint32_t r[4];
                ldsm_x4(r, sB + brow * 128 + ((bc ^ (brow & 7)) << 4));
                b[np * 2][0]     = r[0]; b[np * 2][1]     = r[1];
                b[np * 2 + 1][0] = r[2]; b[np * 2 + 1][1] = r[3];
            }
            #pragma unroll
            for (int mt = 0; mt < 2; mt++)
                #pragma unroll
                for (int nt = 0; nt < 8; nt++)
                    mma_bf16(acc[mt][nt], a[mt], b[nt]);
        }
        __syncthreads();
    }

    // ---- epilogue: write fp32 rows of g_Wh ----
    int row0 = tileRow + warp_m * 32 + (lane >> 2);
    int col0 = warp_n * 64 + (lane & 3) * 2;
    #pragma unroll
    for (int mt = 0; mt < 2; mt++) {
        int r = row0 + mt * 16;
        #pragma unroll
        for (int nt = 0; nt < 8; nt++) {
            int c = col0 + nt * 8;
            if (r < N_NODES)
                *(float2*)&g_Wh[(size_t)r * OUT_F + c] =
                    make_float2(acc[mt][nt][0], acc[mt][nt][1]);
            if (r + 8 < N_NODES)
                *(float2*)&g_Wh[(size_t)(r + 8) * OUT_F + c] =
                    make_float2(acc[mt][nt][2], acc[mt][nt][3]);
        }
    }

    // ---- fused s1/s2: partial dots with a1/a2, quad-reduce, atomicAdd ----
    // p[q]: q = mt*2 + hi8, row = row0 + mt*16 + hi8*8
    float p1[4] = {0.f, 0.f, 0.f, 0.f}, p2[4] = {0.f, 0.f, 0.f, 0.f};
    #pragma unroll
    for (int nt = 0; nt < 8; nt++) {
        int c = col0 + nt * 8;
        float a1x = __ldg(&ga[c]),         a1y = __ldg(&ga[c + 1]);
        float a2x = __ldg(&ga[OUT_F + c]), a2y = __ldg(&ga[OUT_F + c + 1]);
        #pragma unroll
        for (int mt = 0; mt < 2; mt++) {
            p1[mt * 2]     += acc[mt][nt][0] * a1x + acc[mt][nt][1] * a1y;
            p1[mt * 2 + 1] += acc[mt][nt][2] * a1x + acc[mt][nt][3] * a1y;
            p2[mt * 2]     += acc[mt][nt][0] * a2x + acc[mt][nt][1] * a2y;
            p2[mt * 2 + 1] += acc[mt][nt][2] * a2x + acc[mt][nt][3] * a2y;
        }
    }
    #pragma unroll
    for (int q = 0; q < 4; q++) {
        p1[q] += __shfl_xor_sync(0xFFFFFFFFu, p1[q], 1);
        p1[q] += __shfl_xor_sync(0xFFFFFFFFu, p1[q], 2);
        p2[q] += __shfl_xor_sync(0xFFFFFFFFu, p2[q], 1);
        p2[q] += __shfl_xor_sync(0xFFFFFFFFu, p2[q], 2);
    }
    if ((lane & 3) == 0) {
        #pragma unroll
        for (int q = 0; q < 4; q++) {
            int r = row0 + (q >> 1) * 16 + (q & 1) * 8;
            if (r < N_NODES) {
                atomicAdd(&g_s1[r], p1[q]);
                atomicAdd(&g_s2[r], p2[q]);
            }
        }
    }
}

// ---------------- dtype detection for edge_index -----------------------------
__global__ void detect_kernel(const int* __restrict__ ei) {
    __shared__ int any;
    if (threadIdx.x == 0) any = 0;
    __syncthreads();
    for (int i = threadIdx.x; i < 2048; i += blockDim.x)
        if (ei[2 * i + 1] != 0) any = 1;
    __syncthreads();
    if (threadIdx.x == 0) g_is64 = any ? 0 : 1;
}

__global__ void init_cnt_kernel() {
    int i = blockIdx.x * blockDim.x + threadIdx.x;
    if (i < N_NODES) g_cnt[i] = 0;
}

__device__ __forceinline__ void load_edge(const void* ei, int e, int& s, int& d) {
    if (g_is64) {
        const long long* p = (const long long*)ei;
        s = (int)p[e];
        d = (int)p[NUM_E + e];
    } else {
        const int* p = (const int*)ei;
        s = p[e];
        d = p[NUM_E + e];
    }
}

// ---------------- CSR build ----------------------------------------------------
__global__ __launch_bounds__(256) void hist_kernel(const void* __restrict__ ei) {
    int e = blockIdx.x * blockDim.x + threadIdx.x;
    if (e >= NUM_E) return;
    int s, d;
    load_edge(ei, e, s, d);
    atomicAdd(&g_cnt[s], 1);
}

__global__ __launch_bounds__(1024) void scan_kernel() {
    __shared__ int warpsum[32];
    __shared__ int carry_sm;
    const int tid  = threadIdx.x;
    const int lane = tid & 31;
    const int wid  = tid >> 5;
    if (tid == 0) carry_sm = 0;
    __syncthreads();

    for (int chunk = 0; chunk < N_NODES; chunk += 1024) {
        int i = chunk + tid;
        int v = (i < N_NODES) ? g_cnt[i] : 0;
        int x = v;
        #pragma unroll
        for (int o = 1; o < 32; o <<= 1) {
            int y = __shfl_up_sync(0xFFFFFFFFu, x, o);
            if (lane >= o) x += y;
        }
        if (lane == 31) warpsum[wid] = x;
        __syncthreads();
        if (wid == 0) {
            int s = warpsum[lane];
            #pragma unroll
            for (int o = 1; o < 32; o <<= 1) {
                int y = __shfl_up_sync(0xFFFFFFFFu, s, o);
                if (lane >= o) s += y;
            }
            warpsum[lane] = s;
        }
        __syncthreads();
        int base  = (wid > 0) ? warpsum[wid - 1] : 0;
        int carry = carry_sm;
        int excl  = carry + base + x - v;
        if (i < N_NODES) {
            g_off[i]    = excl;
            g_cursor[i] = excl;
        }
        __syncthreads();
        if (tid == 0) carry_sm = carry + warpsum[31];
        __syncthreads();
    }
    if (tid == 0) g_off[N_NODES] = carry_sm;
}

__global__ __launch_bounds__(256) void fill_kernel(const void* __restrict__ ei) {
    int e = blockIdx.x * blockDim.x + threadIdx.x;
    if (e >= NUM_E) return;
    int s, d;
    load_edge(ei, e, s, d);
    float lg  = leaky_logit(__ldg(&g_s1[s]) + __ldg(&g_s2[d]));
    int   pos = atomicAdd(&g_cursor[s], 1);
    g_csr_dst[pos]   = d;
    g_csr_logit[pos] = lg;
}

// ---------------- aggregate: warp per src node --------------------------------
__global__ __launch_bounds__(256) void agg_kernel(float* __restrict__ out) {
    int src  = blockIdx.x * 8 + (threadIdx.x >> 5);
    if (src >= N_NODES) return;
    int lane = threadIdx.x & 31;
    int beg  = g_off[src];
    int end  = g_off[src + 1];

    float4* out4 = (float4*)out;
    if (beg == end) {
        out4[(size_t)src * 32 + lane] = make_float4(0.f, 0.f, 0.f, 0.f);
        return;
    }

    float m = -3.0e38f;
    for (int i = beg + lane; i < end; i += 32)
        m = fmaxf(m, g_csr_logit[i]);
    #pragma unroll
    for (int o = 16; o; o >>= 1)
        m = fmaxf(m, __shfl_xor_sync(0xFFFFFFFFu, m, o));

    const float4* Wh4 = (const float4*)g_Wh;
    float ax = 0.f, ay = 0.f, az = 0.f, aw = 0.f;
    float den = 0.f;

    for (int base = beg; base < end; base += 32) {
        int  idx   = base + lane;
        bool valid = idx < end;
        int   dn = valid ? g_csr_dst[idx] : 0;
        float w  = valid ? __expf(g_csr_logit[idx] - m) : 0.0f;
        den += w;
        int cnt = end - base;
        if (cnt >= 32) {
            #pragma unroll 8
            for (int j = 0; j < 32; j++) {
                int   dj = __shfl_sync(0xFFFFFFFFu, dn, j);
                float wj = __shfl_sync(0xFFFFFFFFu, w,  j);
                float4 v = __ldg(&Wh4[(size_t)dj * 32 + lane]);
                ax += wj * v.x; ay += wj * v.y; az += wj * v.z; aw += wj * v.w;
            }
        } else {
            for (int j = 0; j < cnt; j++) {
                int   dj = __shfl_sync(0xFFFFFFFFu, dn, j);
                float wj = __shfl_sync(0xFFFFFFFFu, w,  j);
                float4 v = __ldg(&Wh4[(size_t)dj * 32 + lane]);
                ax += wj * v.x; ay += wj * v.y; az += wj * v.z; aw += wj * v.w;
            }
        }
    }
    #pragma unroll
    for (int o = 16; o; o >>= 1)
        den += __shfl_xor_sync(0xFFFFFFFFu, den, o);
    float inv = (den > 0.0f) ? (1.0f / den) : 0.0f;

    float4 r;
    r.x = fmaxf(ax * inv, 0.0f);
    r.y = fmaxf(ay * inv, 0.0f);
    r.z = fmaxf(az * inv, 0.0f);
    r.w = fmaxf(aw * inv, 0.0f);
    out4[(size_t)src * 32 + lane] = r;
}

// ---------------- launch ------------------------------------------------------
extern "C" void kernel_launch(void* const* d_in, const int* in_sizes, int n_in,
                              void* d_out, int out_size) {
    const float* h  = (const float*)d_in[0];
    const float* W  = (const float*)d_in[1];
    const float* a  = (const float*)d_in[2];
    const void*  ei = d_in[3];
    float* out = (float*)d_out;

    static cudaStream_t s2 = nullptr;
    static cudaEvent_t evFork = nullptr, evJoin = nullptr;
    if (s2 == nullptr) {
        cudaStreamCreateWithFlags(&s2, cudaStreamNonBlocking);
        cudaEventCreateWithFlags(&evFork, cudaEventDisableTiming);
        cudaEventCreateWithFlags(&evJoin, cudaEventDisableTiming);
        cudaFuncSetAttribute(gemm_mma_kernel,
                             cudaFuncAttributeMaxDynamicSharedMemorySize, GEMM_SMEM);
    }

    // fork: CSR build (needs only edge_index) runs concurrently with GEMM chain
    cudaEventRecord(evFork, 0);
    cudaStreamWaitEvent(s2, evFork, 0);
    detect_kernel<<<1, 256, 0, s2>>>((const int*)ei);
    init_cnt_kernel<<<(N_NODES + 255) / 256, 256, 0, s2>>>();
    hist_kernel<<<(NUM_E + 255) / 256, 256, 0, s2>>>(ei);
    scan_kernel<<<1, 1024, 0, s2>>>();
    cudaEventRecord(evJoin, s2);

    // main stream: convert + GEMM (+ fused s1/s2)
    convert_h_kernel<<<(PAD_ROWS * (IN_F / 8) + 255) / 256, 256>>>(h);
    convert_w_kernel<<<(OUT_F * (IN_F / 8) + 255) / 256, 256>>>(W);
    gemm_mma_kernel<<<N_TILES, 256, GEMM_SMEM>>>(a);

    // join, then edge passes that need both s1/s2 and the CSR offsets
    cudaStreamWaitEvent(0, evJoin, 0);
    fill_kernel<<<(NUM_E + 255) / 256, 256>>>(ei);
    agg_kernel<<<(N_NODES + 7) / 8, 256>>>(out);
}

// round 6
// speedup vs baseline: 3.2882x; 1.0457x over previous
#include <cuda_runtime.h>
#include <cuda_bf16.h>
#include <cuda_fp16.h>
#include <cstdint>

#define N_NODES 50000
#define NUM_E   1600000
#define IN_F    512
#define OUT_F   128
#define NEG_SLOPE 0.01f
#define INV_T     2.0f   // 1 / TEMPERATURE (0.5)

#define TILE_M   128
#define N_TILES  391                   // ceil(50000/128)
#define GBK      64                    // K per chunk
#define NCHUNK   (IN_F / GBK)          // 8

// smem layout (bytes):
//   stage s (s=0,1): [ A_f32 128x64 fp32, rows padded to 272B | Bh 16K | Bl 16K ]
//   conv:            [ Ah 16K | Al 16K ]
#define A_F32_BYTES 34816              // 128 * 272
#define SBH_OFF     34816
#define SBL_OFF     51200
#define STAGE_BYTES 67584
#define CONV_OFF    (2 * STAGE_BYTES)  // 135168
#define GEMM_SMEM   (CONV_OFF + 32768) // 167936

// ---------------- scratch (static device globals; no allocations) -----------
__device__ __half   g_Whh[(size_t)N_NODES * OUT_F];     // 12.8 MB (fp16 Wh)
__device__ __nv_bfloat16 g_Bh[(size_t)OUT_F * IN_F];    // 128 KB (B^T hi)
__device__ __nv_bfloat16 g_Bl[(size_t)OUT_F * IN_F];    // 128 KB (B^T lo)
__device__ float    g_s1[N_NODES];
__device__ float    g_s2[N_NODES];
__device__ int      g_cnt[N_NODES];
__device__ int      g_off[N_NODES + 1];
__device__ int      g_cursor[N_NODES];
__device__ int      g_csr_dst[NUM_E];
__device__ float    g_csr_logit[NUM_E];
__device__ int      g_bsum[64];
__device__ int      g_boff[64];
__device__ int      g_is64;

// ---------------- helpers ----------------------------------------------------
__device__ __forceinline__ uint32_t smem_u32(const void* p) {
    uint32_t a;
    asm("{ .reg .u64 t; cvta.to.shared.u64 t, %1; cvt.u32.u64 %0, t; }" : "=r"(a) : "l"(p));
    return a;
}
__device__ __forceinline__ void cp_async16(uint32_t dst, const void* src) {
    asm volatile("cp.async.cg.shared.global [%0], [%1], 16;"
                 :: "r"(dst), "l"(__cvta_generic_to_global(src)) : "memory");
}
#define CP_COMMIT() asm volatile("cp.async.commit_group;" ::: "memory")
#define CP_WAIT1()  asm volatile("cp.async.wait_group 1;" ::: "memory")

__device__ __forceinline__ void ldsm_x4(uint32_t* r, uint32_t addr) {
    asm volatile("ldmatrix.sync.aligned.m8n8.x4.shared.b16 {%0,%1,%2,%3}, [%4];"
                 : "=r"(r[0]), "=r"(r[1]), "=r"(r[2]), "=r"(r[3]) : "r"(addr));
}
__device__ __forceinline__ void mma_bf16(float* d, const uint32_t* a, const uint32_t* b) {
    asm volatile("mma.sync.aligned.m16n8k16.row.col.f32.bf16.bf16.f32 "
                 "{%0,%1,%2,%3}, {%4,%5,%6,%7}, {%8,%9}, {%0,%1,%2,%3};"
                 : "+f"(d[0]), "+f"(d[1]), "+f"(d[2]), "+f"(d[3])
                 : "r"(a[0]), "r"(a[1]), "r"(a[2]), "r"(a[3]), "r"(b[0]), "r"(b[1]));
}

__device__ __forceinline__ float leaky_logit(float v) {
    v = (v >= 0.0f) ? v : NEG_SLOPE * v;
    return v * INV_T;
}

__device__ __forceinline__ void split8(const float* v, unsigned short* hb, unsigned short* lb) {
    #pragma unroll
    for (int j = 0; j < 8; j++) {
        __nv_bfloat16 hv = __float2bfloat16(v[j]);
        float hf = __bfloat162float(hv);
        __nv_bfloat16 lv = __float2bfloat16(v[j] - hf);
        hb[j] = __bfloat16_as_ushort(hv);
        lb[j] = __bfloat16_as_ushort(lv);
    }
}
__device__ __forceinline__ uint4 pack8(const unsigned short* b) {
    uint4 q;
    q.x = (uint32_t)b[0] | ((uint32_t)b[1] << 16);
    q.y = (uint32_t)b[2] | ((uint32_t)b[3] << 16);
    q.z = (uint32_t)b[4] | ((uint32_t)b[5] << 16);
    q.w = (uint32_t)b[6] | ((uint32_t)b[7] << 16);
    return q;
}

// ---------------- W convert (B^T hi/lo) + zero s1/s2 --------------------------
__global__ __launch_bounds__(256) void convert_w_kernel(const float* __restrict__ W) {
    int idx = blockIdx.x * 256 + threadIdx.x;
    if (idx < N_NODES) { g_s1[idx] = 0.0f; g_s2[idx] = 0.0f; }
    if (idx >= OUT_F * (IN_F / 8)) return;
    int n  = idx / (IN_F / 8);
    int k8 = (idx % (IN_F / 8)) * 8;
    float v[8];
    #pragma unroll
    for (int j = 0; j < 8; j++)
        v[j] = W[(size_t)(k8 + j) * OUT_F + n];
    unsigned short hb[8], lb[8];
    split8(v, hb, lb);
    size_t off = (size_t)n * IN_F + k8;
    *(uint4*)&g_Bh[off] = pack8(hb);
    *(uint4*)&g_Bl[off] = pack8(lb);
}

// ---------------- fused GEMM: Wh(fp16) = h @ W, + s1/s2 ----------------------
// Per K-chunk: cp.async fp32 h tile + Bh/Bl chunk (double buffered), split h to
// bf16 hi/lo in smem, then 3 MMA passes (Ah*Bh, Ah*Bl, Al*Bh) on that chunk.
__global__ __launch_bounds__(256, 1) void gemm_fused_kernel(const float* __restrict__ h,
                                                            const float* __restrict__ ga) {
    extern __shared__ char smx[];
    const int tid  = threadIdx.x;
    const int lane = tid & 31, wid = tid >> 5;
    const int warp_m = wid & 3, warp_n = wid >> 2;   // 4 x 2 warp grid
    const int tileRow = blockIdx.x * TILE_M;
    const uint32_t sbase = smem_u32(smx);

    float acc[2][8][4];
    #pragma unroll
    for (int mt = 0; mt < 2; mt++)
        #pragma unroll
        for (int nt = 0; nt < 8; nt++)
            #pragma unroll
            for (int q = 0; q < 4; q++) acc[mt][nt][q] = 0.0f;

    auto load_stage = [&](int stage, int c) {
        int k0 = c * GBK;
        uint32_t sS = sbase + stage * STAGE_BYTES;
        // fp32 A tile: 128 rows x 64 fp32 (16 x 16B per row), padded stride 272B
        #pragma unroll
        for (int i = 0; i < 8; i++) {
            int cid = tid + i * 256;            // 0..2047
            int row = cid >> 4, cc = cid & 15;
            int gr = tileRow + row;
            if (gr < N_NODES)
                cp_async16(sS + row * 272 + cc * 16,
                           h + (size_t)gr * IN_F + k0 + cc * 4);
        }
        // Bh / Bl chunk: 128 rows(n) x 64 k bf16, swizzled 128B rows
        #pragma unroll
        for (int i = 0; i < 4; i++) {
            int cid = tid + i * 256;            // 0..1023
            int row = cid >> 3, cc = cid & 7;
            uint32_t sw = (uint32_t)((cc ^ (row & 7)) << 4);
            cp_async16(sS + SBH_OFF + row * 128 + sw,
                       g_Bh + (size_t)row * IN_F + k0 + cc * 8);
            cp_async16(sS + SBL_OFF + row * 128 + sw,
                       g_Bl + (size_t)row * IN_F + k0 + cc * 8);
        }
    };

    load_stage(0, 0);
    CP_COMMIT();

    const int mi = lane >> 3, r8 = lane & 7;    // ldmatrix lane decomposition

    for (int c = 0; c < NCHUNK; c++) {
        if (c + 1 < NCHUNK) load_stage((c + 1) & 1, c + 1);
        CP_COMMIT();
        CP_WAIT1();
        __syncthreads();

        uint32_t sS = sbase + (c & 1) * STAGE_BYTES;

        // ---- split fp32 A tile -> bf16 hi/lo into conv buffers ----
        {
            const char* af = smx + (c & 1) * STAGE_BYTES;
            char* ah = smx + CONV_OFF;
            char* al = smx + CONV_OFF + 16384;
            #pragma unroll
            for (int i = 0; i < 4; i++) {
                int cid = tid + i * 256;        // 0..1023
                int row = cid >> 3, cc = cid & 7;
                float v[8];
                *(float4*)&v[0] = *(const float4*)(af + row * 272 + cc * 32);
                *(float4*)&v[4] = *(const float4*)(af + row * 272 + cc * 32 + 16);
                unsigned short hb[8], lb[8];
                split8(v, hb, lb);
                uint32_t sw = (uint32_t)(row * 128 + ((cc ^ (row & 7)) << 4));
                *(uint4*)(ah + sw) = pack8(hb);
                *(uint4*)(al + sw) = pack8(lb);
            }
        }
        __syncthreads();

        // ---- 3 passes: Ah*Bh, Ah*Bl, Al*Bh ----
        #pragma unroll
        for (int p = 0; p < 3; p++) {
            uint32_t aBase = sbase + CONV_OFF + ((p == 2) ? 16384 : 0);
            uint32_t bBase = sS + ((p == 1) ? SBL_OFF : SBH_OFF);
            #pragma unroll
            for (int ks = 0; ks < 4; ks++) {
                uint32_t a[2][4];
                #pragma unroll
                for (int mt = 0; mt < 2; mt++) {
                    int arow = warp_m * 32 + mt * 16 + r8 + (mi & 1) * 8;
                    int ac   = ks * 2 + (mi >> 1);
                    ldsm_x4(a[mt], aBase + arow * 128 + ((ac ^ (arow & 7)) << 4));
                }
                uint32_t b[8][2];
                #pragma unroll
                for (int np = 0; np < 4; np++) {
                    int brow = warp_n * 64 + np * 16 + (mi >> 1) * 8 + r8;
                    int bc   = ks * 2 + (mi & 1);
                    uint32_t r[4];
                    ldsm_x4(r, bBase + brow * 128 + ((bc ^ (brow & 7)) << 4));
                    b[np * 2][0]     = r[0]; b[np * 2][1]     = r[1];
                    b[np * 2 + 1][0] = r[2]; b[np * 2 + 1][1] = r[3];
                }
                #pragma unroll
                for (int mt = 0; mt < 2; mt++)
                    #pragma unroll
                    for (int nt = 0; nt < 8; nt++)
                        mma_bf16(acc[mt][nt], a[mt], b[nt]);
            }
        }
        __syncthreads();
    }

    // ---- epilogue: write fp16 Wh rows ----
    int row0 = tileRow + warp_m * 32 + (lane >> 2);
    int col0 = warp_n * 64 + (lane & 3) * 2;
    #pragma unroll
    for (int mt = 0; mt < 2; mt++) {
        int r = row0 + mt * 16;
        #pragma unroll
        for (int nt = 0; nt < 8; nt++) {
            int cc = col0 + nt * 8;
            if (r < N_NODES)
                *(__half2*)&g_Whh[(size_t)r * OUT_F + cc] =
                    __floats2half2_rn(acc[mt][nt][0], acc[mt][nt][1]);
            if (r + 8 < N_NODES)
                *(__half2*)&g_Whh[(size_t)(r + 8) * OUT_F + cc] =
                    __floats2half2_rn(acc[mt][nt][2], acc[mt][nt][3]);
        }
    }

    // ---- fused s1/s2 (fp32 accumulators): quad-reduce + atomicAdd ----
    float p1[4] = {0.f, 0.f, 0.f, 0.f}, p2[4] = {0.f, 0.f, 0.f, 0.f};
    #pragma unroll
    for (int nt = 0; nt < 8; nt++) {
        int cc = col0 + nt * 8;
        float a1x = __ldg(&ga[cc]),         a1y = __ldg(&ga[cc + 1]);
        float a2x = __ldg(&ga[OUT_F + cc]), a2y = __ldg(&ga[OUT_F + cc + 1]);
        #pragma unroll
        for (int mt = 0; mt < 2; mt++) {
            p1[mt * 2]     += acc[mt][nt][0] * a1x + acc[mt][nt][1] * a1y;
            p1[mt * 2 + 1] += acc[mt][nt][2] * a1x + acc[mt][nt][3] * a1y;
            p2[mt * 2]     += acc[mt][nt][0] * a2x + acc[mt][nt][1] * a2y;
            p2[mt * 2 + 1] += acc[mt][nt][2] * a2x + acc[mt][nt][3] * a2y;
        }
    }
    #pragma unroll
    for (int q = 0; q < 4; q++) {
        p1[q] += __shfl_xor_sync(0xFFFFFFFFu, p1[q], 1);
        p1[q] += __shfl_xor_sync(0xFFFFFFFFu, p1[q], 2);
        p2[q] += __shfl_xor_sync(0xFFFFFFFFu, p2[q], 1);
        p2[q] += __shfl_xor_sync(0xFFFFFFFFu, p2[q], 2);
    }
    if ((lane & 3) == 0) {
        #pragma unroll
        for (int q = 0; q < 4; q++) {
            int r = row0 + (q >> 1) * 16 + (q & 1) * 8;
            if (r < N_NODES) {
                atomicAdd(&g_s1[r], p1[q]);
                atomicAdd(&g_s2[r], p2[q]);
            }
        }
    }
}

// ---------------- dtype detection + CSR side branch ---------------------------
__global__ void detect_kernel(const int* __restrict__ ei) {
    __shared__ int any;
    if (threadIdx.x == 0) any = 0;
    __syncthreads();
    for (int i = threadIdx.x; i < 2048; i += blockDim.x)
        if (ei[2 * i + 1] != 0) any = 1;
    __syncthreads();
    if (threadIdx.x == 0) g_is64 = any ? 0 : 1;
}

__global__ void init_cnt_kernel() {
    int i = blockIdx.x * blockDim.x + threadIdx.x;
    if (i < N_NODES) g_cnt[i] = 0;
}

__device__ __forceinline__ void load_edge(const void* ei, int e, int& s, int& d) {
    if (g_is64) {
        const long long* p = (const long long*)ei;
        s = (int)p[e];
        d = (int)p[NUM_E + e];
    } else {
        const int* p = (const int*)ei;
        s = p[e];
        d = p[NUM_E + e];
    }
}

__global__ __launch_bounds__(256) void hist_kernel(const void* __restrict__ ei) {
    int e = blockIdx.x * blockDim.x + threadIdx.x;
    if (e >= NUM_E) return;
    int s, d;
    load_edge(ei, e, s, d);
    atomicAdd(&g_cnt[s], 1);
}

// hierarchical scan: reduce -> mid -> final
__global__ __launch_bounds__(256) void scan_reduce_kernel() {
    __shared__ int ws[8];
    int tid = threadIdx.x, lane = tid & 31, wid = tid >> 5;
    int s = 0;
    #pragma unroll
    for (int j = 0; j < 4; j++) {
        int i = blockIdx.x * 1024 + j * 256 + tid;
        if (i < N_NODES) s += g_cnt[i];
    }
    #pragma unroll
    for (int o = 16; o; o >>= 1) s += __shfl_xor_sync(0xFFFFFFFFu, s, o);
    if (lane == 0) ws[wid] = s;
    __syncthreads();
    if (tid == 0) {
        int t = 0;
        #pragma unroll
        for (int w = 0; w < 8; w++) t += ws[w];
        g_bsum[blockIdx.x] = t;
    }
}

__global__ void scan_mid_kernel() {
    __shared__ int w0sum;
    int t = threadIdx.x;            // 64 threads
    int lane = t & 31, w = t >> 5;
    const int NBLK = (N_NODES + 1023) / 1024;   // 49
    int v = (t < NBLK) ? g_bsum[t] : 0;
    int x = v;
    #pragma unroll
    for (int o = 1; o < 32; o <<= 1) {
        int y = __shfl_up_sync(0xFFFFFFFFu, x, o);
        if (lane >= o) x += y;
    }
    if (w == 0 && lane == 31) w0sum = x;
    __syncthreads();
    int incl = x + (w == 1 ? w0sum : 0);
    if (t < NBLK) g_boff[t] = incl - v;   // exclusive
}

__global__ __launch_bounds__(1024) void scan_final_kernel() {
    __shared__ int warpsum[32];
    int tid = threadIdx.x, lane = tid & 31, wid = tid >> 5;
    int i = blockIdx.x * 1024 + tid;
    int v = (i < N_NODES) ? g_cnt[i] : 0;
    int x = v;
    #pragma unroll
    for (int o = 1; o < 32; o <<= 1) {
        int y = __shfl_up_sync(0xFFFFFFFFu, x, o);
        if (lane >= o) x += y;
    }
    if (lane == 31) warpsum[wid] = x;
    __syncthreads();
    if (wid == 0) {
        int s = warpsum[lane];
        #pragma unroll
        for (int o = 1; o < 32; o <<= 1) {
            int y = __shfl_up_sync(0xFFFFFFFFu, s, o);
            if (lane >= o) s += y;
        }
        warpsum[lane] = s;
    }
    __syncthreads();
    int base = (wid > 0) ? warpsum[wid - 1] : 0;
    int excl = g_boff[blockIdx.x] + base + x - v;
    if (i < N_NODES) {
        g_off[i]    = excl;
        g_cursor[i] = excl;
    }
    if (blockIdx.x == 0 && tid == 0) g_off[N_NODES] = NUM_E;
}

__global__ __launch_bounds__(256) void fill_kernel(const void* __restrict__ ei) {
    int e = blockIdx.x * blockDim.x + threadIdx.x;
    if (e >= NUM_E) return;
    int s, d;
    load_edge(ei, e, s, d);
    float lg  = leaky_logit(__ldg(&g_s1[s]) + __ldg(&g_s2[d]));
    int   pos = atomicAdd(&g_cursor[s], 1);
    g_csr_dst[pos]   = d;
    g_csr_logit[pos] = lg;
}

// ---------------- aggregate: warp per src node (fp16 gather) ------------------
__global__ __launch_bounds__(256) void agg_kernel(float* __restrict__ out) {
    int src  = blockIdx.x * 8 + (threadIdx.x >> 5);
    if (src >= N_NODES) return;
    int lane = threadIdx.x & 31;
    int beg  = g_off[src];
    int end  = g_off[src + 1];

    float4* out4 = (float4*)out;
    if (beg == end) {
        out4[(size_t)src * 32 + lane] = make_float4(0.f, 0.f, 0.f, 0.f);
        return;
    }

    float m = -3.0e38f;
    for (int i = beg + lane; i < end; i += 32)
        m = fmaxf(m, g_csr_logit[i]);
    #pragma unroll
    for (int o = 16; o; o >>= 1)
        m = fmaxf(m, __shfl_xor_sync(0xFFFFFFFFu, m, o));

    float ax = 0.f, ay = 0.f, az = 0.f, aw = 0.f;
    float den = 0.f;

    for (int base = beg; base < end; base += 32) {
        int  idx   = base + lane;
        bool valid = idx < end;
        int   dn = valid ? g_csr_dst[idx] : 0;
        float w  = valid ? __expf(g_csr_logit[idx] - m) : 0.0f;
        den += w;
        int cnt = end - base;
        if (cnt >= 32) {
            #pragma unroll 8
            for (int j = 0; j < 32; j++) {
                int   dj = __shfl_sync(0xFFFFFFFFu, dn, j);
                float wj = __shfl_sync(0xFFFFFFFFu, w,  j);
                uint2 u = __ldg((const uint2*)&g_Whh[(size_t)dj * OUT_F + lane * 4]);
                float2 f0 = __half22float2(*(__half2*)&u.x);
                float2 f1 = __half22float2(*(__half2*)&u.y);
                ax += wj * f0.x; ay += wj * f0.y; az += wj * f1.x; aw += wj * f1.y;
            }
        } else {
            for (int j = 0; j < cnt; j++) {
                int   dj = __shfl_sync(0xFFFFFFFFu, dn, j);
                float wj = __shfl_sync(0xFFFFFFFFu, w,  j);
                uint2 u = __ldg((const uint2*)&g_Whh[(size_t)dj * OUT_F + lane * 4]);
                float2 f0 = __half22float2(*(__half2*)&u.x);
                float2 f1 = __half22float2(*(__half2*)&u.y);
                ax += wj * f0.x; ay += wj * f0.y; az += wj * f1.x; aw += wj * f1.y;
            }
        }
    }
    #pragma unroll
    for (int o = 16; o; o >>= 1)
        den += __shfl_xor_sync(0xFFFFFFFFu, den, o);
    float inv = (den > 0.0f) ? (1.0f / den) : 0.0f;

    float4 r;
    r.x = fmaxf(ax * inv, 0.0f);
    r.y = fmaxf(ay * inv, 0.0f);
    r.z = fmaxf(az * inv, 0.0f);
    r.w = fmaxf(aw * inv, 0.0f);
    out4[(size_t)src * 32 + lane] = r;
}

// ---------------- launch ------------------------------------------------------
extern "C" void kernel_launch(void* const* d_in, const int* in_sizes, int n_in,
                              void* d_out, int out_size) {
    const float* h  = (const float*)d_in[0];
    const float* W  = (const float*)d_in[1];
    const float* a  = (const float*)d_in[2];
    const void*  ei = d_in[3];
    float* out = (float*)d_out;

    static cudaStream_t s2 = nullptr;
    static cudaEvent_t evFork = nullptr, evJoin = nullptr;
    if (s2 == nullptr) {
        cudaStreamCreateWithFlags(&s2, cudaStreamNonBlocking);
        cudaEventCreateWithFlags(&evFork, cudaEventDisableTiming);
        cudaEventCreateWithFlags(&evJoin, cudaEventDisableTiming);
        cudaFuncSetAttribute(gemm_fused_kernel,
                             cudaFuncAttributeMaxDynamicSharedMemorySize, GEMM_SMEM);
    }

    const int NBLK = (N_NODES + 1023) / 1024;   // 49

    // fork: CSR build (needs only edge_index) overlaps the GEMM chain
    cudaEventRecord(evFork, 0);
    cudaStreamWaitEvent(s2, evFork, 0);
    detect_kernel<<<1, 256, 0, s2>>>((const int*)ei);
    init_cnt_kernel<<<(N_NODES + 255) / 256, 256, 0, s2>>>();
    hist_kernel<<<(NUM_E + 255) / 256, 256, 0, s2>>>(ei);
    scan_reduce_kernel<<<NBLK, 256, 0, s2>>>();
    scan_mid_kernel<<<1, 64, 0, s2>>>();
    scan_final_kernel<<<NBLK, 1024, 0, s2>>>();
    cudaEventRecord(evJoin, s2);

    // main: W convert (+ s1/s2 zero) then fused GEMM
    convert_w_kernel<<<(N_NODES + 255) / 256, 256>>>(W);
    gemm_fused_kernel<<<N_TILES, 256, GEMM_SMEM>>>(h, a);

    // join, then edge passes
    cudaStreamWaitEvent(0, evJoin, 0);
    fill_kernel<<<(NUM_E + 255) / 256, 256>>>(ei);
    agg_kernel<<<(N_NODES + 7) / 8, 256>>>(out);
}

// round 7
// speedup vs baseline: 3.3101x; 1.0066x over previous
#include <cuda_runtime.h>
#include <cuda_bf16.h>
#include <cuda_fp16.h>
#include <cstdint>

#define N_NODES 50000
#define NUM_E   1600000
#define IN_F    512
#define OUT_F   128
#define NEG_SLOPE 0.01f
#define INV_T     2.0f   // 1 / TEMPERATURE (0.5)

#define TILE_M   128
#define N_TILES  391                   // ceil(50000/128)
#define GBK      64                    // K per chunk
#define NCHUNK   (IN_F / GBK)          // 8

// smem layout (bytes):
//   stage s (s=0,1): [ A_f32 128x64 fp32, rows padded to 272B | Bh 16K | Bl 16K ]
//   conv:            [ Ah 16K | Al 16K ]
#define A_F32_BYTES 34816              // 128 * 272
#define SBH_OFF     34816
#define SBL_OFF     51200
#define STAGE_BYTES 67584
#define CONV_OFF    (2 * STAGE_BYTES)  // 135168
#define GEMM_SMEM   (CONV_OFF + 32768) // 167936

// ---------------- scratch (static device globals; no allocations) -----------
__device__ __half   g_Whh[(size_t)N_NODES * OUT_F];     // 12.8 MB (fp16 Wh)
__device__ __nv_bfloat16 g_Bh[(size_t)OUT_F * IN_F];    // 128 KB (B^T hi)
__device__ __nv_bfloat16 g_Bl[(size_t)OUT_F * IN_F];    // 128 KB (B^T lo)
__device__ float    g_u1[IN_F];
__device__ float    g_u2[IN_F];
__device__ float    g_s1[N_NODES];
__device__ float    g_s2[N_NODES];
__device__ int      g_cnt[N_NODES];
__device__ int      g_off[N_NODES + 1];
__device__ int      g_cursor[N_NODES];
__device__ int      g_csr_dst[NUM_E];
__device__ float    g_csr_w[NUM_E];                     // exp(logit) per edge
__device__ int      g_bsum[64];
__device__ int      g_boff[64];
__device__ int      g_is64;

// ---------------- helpers ----------------------------------------------------
__device__ __forceinline__ uint32_t smem_u32(const void* p) {
    uint32_t a;
    asm("{ .reg .u64 t; cvta.to.shared.u64 t, %1; cvt.u32.u64 %0, t; }" : "=r"(a) : "l"(p));
    return a;
}
__device__ __forceinline__ void cp_async16(uint32_t dst, const void* src) {
    asm volatile("cp.async.cg.shared.global [%0], [%1], 16;"
                 :: "r"(dst), "l"(__cvta_generic_to_global(src)) : "memory");
}
#define CP_COMMIT() asm volatile("cp.async.commit_group;" ::: "memory")
#define CP_WAIT1()  asm volatile("cp.async.wait_group 1;" ::: "memory")

__device__ __forceinline__ void ldsm_x4(uint32_t* r, uint32_t addr) {
    asm volatile("ldmatrix.sync.aligned.m8n8.x4.shared.b16 {%0,%1,%2,%3}, [%4];"
                 : "=r"(r[0]), "=r"(r[1]), "=r"(r[2]), "=r"(r[3]) : "r"(addr));
}
__device__ __forceinline__ void mma_bf16(float* d, const uint32_t* a, const uint32_t* b) {
    asm volatile("mma.sync.aligned.m16n8k16.row.col.f32.bf16.bf16.f32 "
                 "{%0,%1,%2,%3}, {%4,%5,%6,%7}, {%8,%9}, {%0,%1,%2,%3};"
                 : "+f"(d[0]), "+f"(d[1]), "+f"(d[2]), "+f"(d[3])
                 : "r"(a[0]), "r"(a[1]), "r"(a[2]), "r"(a[3]), "r"(b[0]), "r"(b[1]));
}

__device__ __forceinline__ float leaky_logit(float v) {
    v = (v >= 0.0f) ? v : NEG_SLOPE * v;
    return v * INV_T;
}

__device__ __forceinline__ void split8(const float* v, unsigned short* hb, unsigned short* lb) {
    #pragma unroll
    for (int j = 0; j < 8; j++) {
        __nv_bfloat16 hv = __float2bfloat16(v[j]);
        float hf = __bfloat162float(hv);
        __nv_bfloat16 lv = __float2bfloat16(v[j] - hf);
        hb[j] = __bfloat16_as_ushort(hv);
        lb[j] = __bfloat16_as_ushort(lv);
    }
}
__device__ __forceinline__ uint4 pack8(const unsigned short* b) {
    uint4 q;
    q.x = (uint32_t)b[0] | ((uint32_t)b[1] << 16);
    q.y = (uint32_t)b[2] | ((uint32_t)b[3] << 16);
    q.z = (uint32_t)b[4] | ((uint32_t)b[5] << 16);
    q.w = (uint32_t)b[6] | ((uint32_t)b[7] << 16);
    return q;
}

// ---------------- W convert (B^T hi/lo) ---------------------------------------
__global__ __launch_bounds__(256) void convert_w_kernel(const float* __restrict__ W) {
    int idx = blockIdx.x * 256 + threadIdx.x;
    if (idx >= OUT_F * (IN_F / 8)) return;
    int n  = idx / (IN_F / 8);
    int k8 = (idx % (IN_F / 8)) * 8;
    float v[8];
    #pragma unroll
    for (int j = 0; j < 8; j++)
        v[j] = W[(size_t)(k8 + j) * OUT_F + n];
    unsigned short hb[8], lb[8];
    split8(v, hb, lb);
    size_t off = (size_t)n * IN_F + k8;
    *(uint4*)&g_Bh[off] = pack8(hb);
    *(uint4*)&g_Bl[off] = pack8(lb);
}

// ---------------- u1 = W @ a1, u2 = W @ a2 (warp per k row) -------------------
__global__ __launch_bounds__(256) void u_kernel(const float* __restrict__ W,
                                                const float* __restrict__ a) {
    int k    = blockIdx.x * 8 + (threadIdx.x >> 5);
    int lane = threadIdx.x & 31;
    if (k >= IN_F) return;
    float4 w  = *(const float4*)&W[(size_t)k * OUT_F + lane * 4];
    float4 a1 = *(const float4*)&a[lane * 4];
    float4 a2 = *(const float4*)&a[OUT_F + lane * 4];
    float p1 = w.x * a1.x + w.y * a1.y + w.z * a1.z + w.w * a1.w;
    float p2 = w.x * a2.x + w.y * a2.y + w.z * a2.z + w.w * a2.w;
    #pragma unroll
    for (int o = 16; o; o >>= 1) {
        p1 += __shfl_down_sync(0xFFFFFFFFu, p1, o);
        p2 += __shfl_down_sync(0xFFFFFFFFu, p2, o);
    }
    if (lane == 0) { g_u1[k] = p1; g_u2[k] = p2; }
}

// ---------------- s1 = h @ u1, s2 = h @ u2 (warp per row) ---------------------
__global__ __launch_bounds__(256) void matvec_kernel(const float* __restrict__ h) {
    __shared__ float su1[IN_F], su2[IN_F];
    int tid = threadIdx.x;
    if (tid < IN_F / 2) {
        ((float2*)su1)[tid] = ((const float2*)g_u1)[tid];
        ((float2*)su2)[tid] = ((const float2*)g_u2)[tid];
    }
    __syncthreads();
    int row  = blockIdx.x * 8 + (tid >> 5);
    int lane = tid & 31;
    if (row >= N_NODES) return;
    float p1 = 0.f, p2 = 0.f;
    #pragma unroll
    for (int i = 0; i < 4; i++) {
        float4 v  = __ldg((const float4*)&h[(size_t)row * IN_F + i * 128 + lane * 4]);
        float4 q1 = *(const float4*)&su1[i * 128 + lane * 4];
        float4 q2 = *(const float4*)&su2[i * 128 + lane * 4];
        p1 += v.x * q1.x + v.y * q1.y + v.z * q1.z + v.w * q1.w;
        p2 += v.x * q2.x + v.y * q2.y + v.z * q2.z + v.w * q2.w;
    }
    #pragma unroll
    for (int o = 16; o; o >>= 1) {
        p1 += __shfl_down_sync(0xFFFFFFFFu, p1, o);
        p2 += __shfl_down_sync(0xFFFFFFFFu, p2, o);
    }
    if (lane == 0) { g_s1[row] = p1; g_s2[row] = p2; }
}

// ---------------- fused GEMM: Wh(fp16) = h @ W --------------------------------
__global__ __launch_bounds__(256, 1) void gemm_fused_kernel(const float* __restrict__ h) {
    extern __shared__ char smx[];
    const int tid  = threadIdx.x;
    const int lane = tid & 31, wid = tid >> 5;
    const int warp_m = wid & 3, warp_n = wid >> 2;   // 4 x 2 warp grid
    const int tileRow = blockIdx.x * TILE_M;
    const uint32_t sbase = smem_u32(smx);

    float acc[2][8][4];
    #pragma unroll
    for (int mt = 0; mt < 2; mt++)
        #pragma unroll
        for (int nt = 0; nt < 8; nt++)
            #pragma unroll
            for (int q = 0; q < 4; q++) acc[mt][nt][q] = 0.0f;

    auto load_stage = [&](int stage, int c) {
        int k0 = c * GBK;
        uint32_t sS = sbase + stage * STAGE_BYTES;
        #pragma unroll
        for (int i = 0; i < 8; i++) {
            int cid = tid + i * 256;            // 0..2047
            int row = cid >> 4, cc = cid & 15;
            int gr = tileRow + row;
            if (gr < N_NODES)
                cp_async16(sS + row * 272 + cc * 16,
                           h + (size_t)gr * IN_F + k0 + cc * 4);
        }
        #pragma unroll
        for (int i = 0; i < 4; i++) {
            int cid = tid + i * 256;            // 0..1023
            int row = cid >> 3, cc = cid & 7;
            uint32_t sw = (uint32_t)((cc ^ (row & 7)) << 4);
            cp_async16(sS + SBH_OFF + row * 128 + sw,
                       g_Bh + (size_t)row * IN_F + k0 + cc * 8);
            cp_async16(sS + SBL_OFF + row * 128 + sw,
                       g_Bl + (size_t)row * IN_F + k0 + cc * 8);
        }
    };

    load_stage(0, 0);
    CP_COMMIT();

    const int mi = lane >> 3, r8 = lane & 7;

    for (int c = 0; c < NCHUNK; c++) {
        if (c + 1 < NCHUNK) load_stage((c + 1) & 1, c + 1);
        CP_COMMIT();
        CP_WAIT1();
        __syncthreads();

        uint32_t sS = sbase + (c & 1) * STAGE_BYTES;

        // split fp32 A tile -> bf16 hi/lo
        {
            const char* af = smx + (c & 1) * STAGE_BYTES;
            char* ah = smx + CONV_OFF;
            char* al = smx + CONV_OFF + 16384;
            #pragma unroll
            for (int i = 0; i < 4; i++) {
                int cid = tid + i * 256;
                int row = cid >> 3, cc = cid & 7;
                float v[8];
                *(float4*)&v[0] = *(const float4*)(af + row * 272 + cc * 32);
                *(float4*)&v[4] = *(const float4*)(af + row * 272 + cc * 32 + 16);
                unsigned short hb[8], lb[8];
                split8(v, hb, lb);
                uint32_t sw = (uint32_t)(row * 128 + ((cc ^ (row & 7)) << 4));
                *(uint4*)(ah + sw) = pack8(hb);
                *(uint4*)(al + sw) = pack8(lb);
            }
        }
        __syncthreads();

        #pragma unroll
        for (int p = 0; p < 3; p++) {           // Ah*Bh, Ah*Bl, Al*Bh
            uint32_t aBase = sbase + CONV_OFF + ((p == 2) ? 16384 : 0);
            uint32_t bBase = sS + ((p == 1) ? SBL_OFF : SBH_OFF);
            #pragma unroll
            for (int ks = 0; ks < 4; ks++) {
                uint32_t a[2][4];
                #pragma unroll
                for (int mt = 0; mt < 2; mt++) {
                    int arow = warp_m * 32 + mt * 16 + r8 + (mi & 1) * 8;
                    int ac   = ks * 2 + (mi >> 1);
                    ldsm_x4(a[mt], aBase + arow * 128 + ((ac ^ (arow & 7)) << 4));
                }
                uint32_t b[8][2];
                #pragma unroll
                for (int np = 0; np < 4; np++) {
                    int brow = warp_n * 64 + np * 16 + (mi >> 1) * 8 + r8;
                    int bc   = ks * 2 + (mi & 1);
                    uint32_t r[4];
                    ldsm_x4(r, bBase + brow * 128 + ((bc ^ (brow & 7)) << 4));
                    b[np * 2][0]     = r[0]; b[np * 2][1]     = r[1];
                    b[np * 2 + 1][0] = r[2]; b[np * 2 + 1][1] = r[3];
                }
                #pragma unroll
                for (int mt = 0; mt < 2; mt++)
                    #pragma unroll
                    for (int nt = 0; nt < 8; nt++)
                        mma_bf16(acc[mt][nt], a[mt], b[nt]);
            }
        }
        __syncthreads();
    }

    // epilogue: fp16 Wh rows
    int row0 = tileRow + warp_m * 32 + (lane >> 2);
    int col0 = warp_n * 64 + (lane & 3) * 2;
    #pragma unroll
    for (int mt = 0; mt < 2; mt++) {
        int r = row0 + mt * 16;
        #pragma unroll
        for (int nt = 0; nt < 8; nt++) {
            int cc = col0 + nt * 8;
            if (r < N_NODES)
                *(__half2*)&g_Whh[(size_t)r * OUT_F + cc] =
                    __floats2half2_rn(acc[mt][nt][0], acc[mt][nt][1]);
            if (r + 8 < N_NODES)
                *(__half2*)&g_Whh[(size_t)(r + 8) * OUT_F + cc] =
                    __floats2half2_rn(acc[mt][nt][2], acc[mt][nt][3]);
        }
    }
}

// ---------------- dtype detection + CSR side branch ---------------------------
__global__ void detect_kernel(const int* __restrict__ ei) {
    __shared__ int any;
    if (threadIdx.x == 0) any = 0;
    __syncthreads();
    for (int i = threadIdx.x; i < 2048; i += blockDim.x)
        if (ei[2 * i + 1] != 0) any = 1;
    __syncthreads();
    if (threadIdx.x == 0) g_is64 = any ? 0 : 1;
}

__global__ void init_cnt_kernel() {
    int i = blockIdx.x * blockDim.x + threadIdx.x;
    if (i < N_NODES) g_cnt[i] = 0;
}

__device__ __forceinline__ void load_edge(const void* ei, int e, int& s, int& d) {
    if (g_is64) {
        const long long* p = (const long long*)ei;
        s = (int)p[e];
        d = (int)p[NUM_E + e];
    } else {
        const int* p = (const int*)ei;
        s = p[e];
        d = p[NUM_E + e];
    }
}

__global__ __launch_bounds__(256) void hist_kernel(const void* __restrict__ ei) {
    int e = blockIdx.x * blockDim.x + threadIdx.x;
    if (e >= NUM_E) return;
    int s, d;
    load_edge(ei, e, s, d);
    atomicAdd(&g_cnt[s], 1);
}

__global__ __launch_bounds__(256) void scan_reduce_kernel() {
    __shared__ int ws[8];
    int tid = threadIdx.x, lane = tid & 31, wid = tid >> 5;
    int s = 0;
    #pragma unroll
    for (int j = 0; j < 4; j++) {
        int i = blockIdx.x * 1024 + j * 256 + tid;
        if (i < N_NODES) s += g_cnt[i];
    }
    #pragma unroll
    for (int o = 16; o; o >>= 1) s += __shfl_xor_sync(0xFFFFFFFFu, s, o);
    if (lane == 0) ws[wid] = s;
    __syncthreads();
    if (tid == 0) {
        int t = 0;
        #pragma unroll
        for (int w = 0; w < 8; w++) t += ws[w];
        g_bsum[blockIdx.x] = t;
    }
}

__global__ void scan_mid_kernel() {
    __shared__ int w0sum;
    int t = threadIdx.x;            // 64 threads
    int lane = t & 31, w = t >> 5;
    const int NBLK = (N_NODES + 1023) / 1024;   // 49
    int v = (t < NBLK) ? g_bsum[t] : 0;
    int x = v;
    #pragma unroll
    for (int o = 1; o < 32; o <<= 1) {
        int y = __shfl_up_sync(0xFFFFFFFFu, x, o);
        if (lane >= o) x += y;
    }
    if (w == 0 && lane == 31) w0sum = x;
    __syncthreads();
    int incl = x + (w == 1 ? w0sum : 0);
    if (t < NBLK) g_boff[t] = incl - v;   // exclusive
}

__global__ __launch_bounds__(1024) void scan_final_kernel() {
    __shared__ int warpsum[32];
    int tid = threadIdx.x, lane = tid & 31, wid = tid >> 5;
    int i = blockIdx.x * 1024 + tid;
    int v = (i < N_NODES) ? g_cnt[i] : 0;
    int x = v;
    #pragma unroll
    for (int o = 1; o < 32; o <<= 1) {
        int y = __shfl_up_sync(0xFFFFFFFFu, x, o);
        if (lane >= o) x += y;
    }
    if (lane == 31) warpsum[wid] = x;
    __syncthreads();
    if (wid == 0) {
        int s = warpsum[lane];
        #pragma unroll
        for (int o = 1; o < 32; o <<= 1) {
            int y = __shfl_up_sync(0xFFFFFFFFu, s, o);
            if (lane >= o) s += y;
        }
        warpsum[lane] = s;
    }
    __syncthreads();
    int base = (wid > 0) ? warpsum[wid - 1] : 0;
    int excl = g_boff[blockIdx.x] + base + x - v;
    if (i < N_NODES) {
        g_off[i]    = excl;
        g_cursor[i] = excl;
    }
    if (blockIdx.x == 0 && tid == 0) g_off[N_NODES] = NUM_E;
}

// fill: store (dst, w = exp(logit)) — no segment max needed (range-safe)
__global__ __launch_bounds__(256) void fill_kernel(const void* __restrict__ ei) {
    int e = blockIdx.x * blockDim.x + threadIdx.x;
    if (e >= NUM_E) return;
    int s, d;
    load_edge(ei, e, s, d);
    float lg  = leaky_logit(__ldg(&g_s1[s]) + __ldg(&g_s2[d]));
    int   pos = atomicAdd(&g_cursor[s], 1);
    g_csr_dst[pos] = d;
    g_csr_w[pos]   = __expf(lg);
}

// ---------------- aggregate: warp per src node (single pass) ------------------
__global__ __launch_bounds__(256) void agg_kernel(float* __restrict__ out) {
    int src  = blockIdx.x * 8 + (threadIdx.x >> 5);
    if (src >= N_NODES) return;
    int lane = threadIdx.x & 31;
    int beg  = g_off[src];
    int end  = g_off[src + 1];

    float4* out4 = (float4*)out;
    if (beg == end) {
        out4[(size_t)src * 32 + lane] = make_float4(0.f, 0.f, 0.f, 0.f);
        return;
    }

    float ax = 0.f, ay = 0.f, az = 0.f, aw = 0.f;
    float den = 0.f;

    for (int base = beg; base < end; base += 32) {
        int  idx   = base + lane;
        bool valid = idx < end;
        int   dn = valid ? g_csr_dst[idx] : 0;
        float w  = valid ? g_csr_w[idx]   : 0.0f;
        den += w;
        int cnt = end - base;
        if (cnt >= 32) {
            #pragma unroll 8
            for (int j = 0; j < 32; j++) {
                int   dj = __shfl_sync(0xFFFFFFFFu, dn, j);
                float wj = __shfl_sync(0xFFFFFFFFu, w,  j);
                uint2 u = __ldg((const uint2*)&g_Whh[(size_t)dj * OUT_F + lane * 4]);
                float2 f0 = __half22float2(*(__half2*)&u.x);
                float2 f1 = __half22float2(*(__half2*)&u.y);
                ax += wj * f0.x; ay += wj * f0.y; az += wj * f1.x; aw += wj * f1.y;
            }
        } else {
            for (int j = 0; j < cnt; j++) {
                int   dj = __shfl_sync(0xFFFFFFFFu, dn, j);
                float wj = __shfl_sync(0xFFFFFFFFu, w,  j);
                uint2 u = __ldg((const uint2*)&g_Whh[(size_t)dj * OUT_F + lane * 4]);
                float2 f0 = __half22float2(*(__half2*)&u.x);
                float2 f1 = __half22float2(*(__half2*)&u.y);
                ax += wj * f0.x; ay += wj * f0.y; az += wj * f1.x; aw += wj * f1.y;
            }
        }
    }
    #pragma unroll
    for (int o = 16; o; o >>= 1)
        den += __shfl_xor_sync(0xFFFFFFFFu, den, o);
    float inv = (den > 0.0f) ? (1.0f / den) : 0.0f;

    float4 r;
    r.x = fmaxf(ax * inv, 0.0f);
    r.y = fmaxf(ay * inv, 0.0f);
    r.z = fmaxf(az * inv, 0.0f);
    r.w = fmaxf(aw * inv, 0.0f);
    out4[(size_t)src * 32 + lane] = r;
}

// ---------------- launch ------------------------------------------------------
extern "C" void kernel_launch(void* const* d_in, const int* in_sizes, int n_in,
                              void* d_out, int out_size) {
    const float* h  = (const float*)d_in[0];
    const float* W  = (const float*)d_in[1];
    const float* a  = (const float*)d_in[2];
    const void*  ei = d_in[3];
    float* out = (float*)d_out;

    static cudaStream_t s2 = nullptr, s3 = nullptr;
    static cudaEvent_t evFork = nullptr, evJoin = nullptr, ev3 = nullptr;
    if (s2 == nullptr) {
        cudaStreamCreateWithFlags(&s2, cudaStreamNonBlocking);
        cudaStreamCreateWithFlags(&s3, cudaStreamNonBlocking);
        cudaEventCreateWithFlags(&evFork, cudaEventDisableTiming);
        cudaEventCreateWithFlags(&evJoin, cudaEventDisableTiming);
        cudaEventCreateWithFlags(&ev3, cudaEventDisableTiming);
        cudaFuncSetAttribute(gemm_fused_kernel,
                             cudaFuncAttributeMaxDynamicSharedMemorySize, GEMM_SMEM);
    }

    const int NBLK = (N_NODES + 1023) / 1024;   // 49

    cudaEventRecord(evFork, 0);
    cudaStreamWaitEvent(s2, evFork, 0);
    cudaStreamWaitEvent(s3, evFork, 0);

    // s3: s1/s2 via associativity (u = W@a, s = h@u)
    u_kernel<<<(IN_F + 7) / 8, 256, 0, s3>>>(W, a);
    matvec_kernel<<<(N_NODES + 7) / 8, 256, 0, s3>>>(h);
    cudaEventRecord(ev3, s3);

    // s2: CSR build, then fill (needs s1/s2 from s3)
    detect_kernel<<<1, 256, 0, s2>>>((const int*)ei);
    init_cnt_kernel<<<(N_NODES + 255) / 256, 256, 0, s2>>>();
    hist_kernel<<<(NUM_E + 255) / 256, 256, 0, s2>>>(ei);
    scan_reduce_kernel<<<NBLK, 256, 0, s2>>>();
    scan_mid_kernel<<<1, 64, 0, s2>>>();
    scan_final_kernel<<<NBLK, 1024, 0, s2>>>();
    cudaStreamWaitEvent(s2, ev3, 0);
    fill_kernel<<<(NUM_E + 255) / 256, 256, 0, s2>>>(ei);
    cudaEventRecord(evJoin, s2);

    // main: W convert + GEMM (concurrent with the whole side branch)
    convert_w_kernel<<<(OUT_F * (IN_F / 8) + 255) / 256, 256>>>(W);
    gemm_fused_kernel<<<N_TILES, 256, GEMM_SMEM>>>(h);

    // join, then aggregate
    cudaStreamWaitEvent(0, evJoin, 0);
    agg_kernel<<<(N_NODES + 7) / 8, 256>>>(out);
}

// round 8
// speedup vs baseline: 3.5757x; 1.0802x over previous
#include <cuda_runtime.h>
#include <cuda_fp16.h>
#include <cstdint>

#define N_NODES 50000
#define NUM_E   1600000
#define IN_F    512
#define OUT_F   128
#define NEG_SLOPE 0.01f
#define INV_T     2.0f   // 1 / TEMPERATURE (0.5)

#define TILE_M   128
#define N_TILES  391                   // ceil(50000/128)
#define PAD_ROWS (N_TILES * TILE_M)    // 50048
#define GBK      64                    // K per chunk
#define NCHUNK   (IN_F / GBK)          // 8

// smem: stage = [ A 16K | Bh 16K | Bl 16K ] fp16 swizzled; double buffered
#define SBH_OFF     16384
#define SBL_OFF     32768
#define STAGE_BYTES 49152
#define GEMM_SMEM   (2 * STAGE_BYTES)  // 96 KB -> 2 CTAs/SM

// ---------------- scratch (static device globals; no allocations) -----------
__device__ __half   g_Whh[(size_t)N_NODES * OUT_F];     // 12.8 MB (fp16 Wh)
__device__ __half   g_A16[(size_t)PAD_ROWS * IN_F];     // 51.2 MB (fp16 h)
__device__ __half   g_Bh16[(size_t)OUT_F * IN_F];       // 128 KB (B^T hi fp16)
__device__ __half   g_Bl16[(size_t)OUT_F * IN_F];       // 128 KB (B^T lo fp16)
__device__ float    g_u1[IN_F];
__device__ float    g_u2[IN_F];
__device__ float    g_s1[N_NODES];
__device__ float    g_s2[N_NODES];
__device__ int      g_cnt[N_NODES];
__device__ int      g_off[N_NODES + 1];
__device__ int      g_cursor[N_NODES];
__device__ int      g_csr_dst[NUM_E];
__device__ float    g_csr_w[NUM_E];                     // exp(logit) per edge
__device__ int      g_bsum[64];
__device__ int      g_boff[64];
__device__ int      g_is64;

// ---------------- helpers ----------------------------------------------------
__device__ __forceinline__ uint32_t smem_u32(const void* p) {
    uint32_t a;
    asm("{ .reg .u64 t; cvta.to.shared.u64 t, %1; cvt.u32.u64 %0, t; }" : "=r"(a) : "l"(p));
    return a;
}
__device__ __forceinline__ void cp_async16(uint32_t dst, const void* src) {
    asm volatile("cp.async.cg.shared.global [%0], [%1], 16;"
                 :: "r"(dst), "l"(__cvta_generic_to_global(src)) : "memory");
}
#define CP_COMMIT() asm volatile("cp.async.commit_group;" ::: "memory")
#define CP_WAIT1()  asm volatile("cp.async.wait_group 1;" ::: "memory")

__device__ __forceinline__ void ldsm_x4(uint32_t* r, uint32_t addr) {
    asm volatile("ldmatrix.sync.aligned.m8n8.x4.shared.b16 {%0,%1,%2,%3}, [%4];"
                 : "=r"(r[0]), "=r"(r[1]), "=r"(r[2]), "=r"(r[3]) : "r"(addr));
}
__device__ __forceinline__ void mma_f16(float* d, const uint32_t* a, const uint32_t* b) {
    asm volatile("mma.sync.aligned.m16n8k16.row.col.f32.f16.f16.f32 "
                 "{%0,%1,%2,%3}, {%4,%5,%6,%7}, {%8,%9}, {%0,%1,%2,%3};"
                 : "+f"(d[0]), "+f"(d[1]), "+f"(d[2]), "+f"(d[3])
                 : "r"(a[0]), "r"(a[1]), "r"(a[2]), "r"(a[3]), "r"(b[0]), "r"(b[1]));
}

__device__ __forceinline__ float leaky_logit(float v) {
    v = (v >= 0.0f) ? v : NEG_SLOPE * v;
    return v * INV_T;
}

// ---------------- h -> fp16 (padded rows zeroed) ------------------------------
__global__ __launch_bounds__(256) void convert_h16_kernel(const float* __restrict__ h) {
    int idx = blockIdx.x * 256 + threadIdx.x;      // one per 8 elems
    if (idx >= PAD_ROWS * (IN_F / 8)) return;
    int r  = idx >> 6;
    int c8 = idx & 63;
    uint4 q;
    if (r < N_NODES) {
        const float4* p = (const float4*)&h[(size_t)r * IN_F + c8 * 8];
        float4 x = p[0], y = p[1];
        __half2 h0 = __floats2half2_rn(x.x, x.y);
        __half2 h1 = __floats2half2_rn(x.z, x.w);
        __half2 h2 = __floats2half2_rn(y.x, y.y);
        __half2 h3 = __floats2half2_rn(y.z, y.w);
        q.x = *(uint32_t*)&h0; q.y = *(uint32_t*)&h1;
        q.z = *(uint32_t*)&h2; q.w = *(uint32_t*)&h3;
    } else {
        q = make_uint4(0, 0, 0, 0);
    }
    *(uint4*)&g_A16[(size_t)r * IN_F + c8 * 8] = q;
}

// ---------------- W -> B^T fp16 hi/lo split ------------------------------------
__global__ __launch_bounds__(256) void convert_w_kernel(const float* __restrict__ W) {
    int idx = blockIdx.x * 256 + threadIdx.x;
    if (idx >= OUT_F * (IN_F / 8)) return;
    int n  = idx / (IN_F / 8);
    int k8 = (idx % (IN_F / 8)) * 8;
    unsigned short hb[8], lb[8];
    #pragma unroll
    for (int j = 0; j < 8; j++) {
        float v = W[(size_t)(k8 + j) * OUT_F + n];
        __half hv = __float2half_rn(v);
        __half lv = __float2half_rn(v - __half2float(hv));
        hb[j] = *(unsigned short*)&hv;
        lb[j] = *(unsigned short*)&lv;
    }
    uint4 qh, ql;
    qh.x = hb[0] | ((uint32_t)hb[1] << 16); qh.y = hb[2] | ((uint32_t)hb[3] << 16);
    qh.z = hb[4] | ((uint32_t)hb[5] << 16); qh.w = hb[6] | ((uint32_t)hb[7] << 16);
    ql.x = lb[0] | ((uint32_t)lb[1] << 16); ql.y = lb[2] | ((uint32_t)lb[3] << 16);
    ql.z = lb[4] | ((uint32_t)lb[5] << 16); ql.w = lb[6] | ((uint32_t)lb[7] << 16);
    size_t off = (size_t)n * IN_F + k8;
    *(uint4*)&g_Bh16[off] = qh;
    *(uint4*)&g_Bl16[off] = ql;
}

// ---------------- GEMM: Wh(fp16) = A16 @ (Bh + Bl) ----------------------------
__global__ __launch_bounds__(256, 2) void gemm_f16_kernel() {
    extern __shared__ char smx[];
    const int tid  = threadIdx.x;
    const int lane = tid & 31, wid = tid >> 5;
    const int warp_m = wid & 3, warp_n = wid >> 2;   // 4 x 2 warp grid
    const int tileRow = blockIdx.x * TILE_M;
    const uint32_t sbase = smem_u32(smx);

    float acc[2][8][4];
    #pragma unroll
    for (int mt = 0; mt < 2; mt++)
        #pragma unroll
        for (int nt = 0; nt < 8; nt++)
            #pragma unroll
            for (int q = 0; q < 4; q++) acc[mt][nt][q] = 0.0f;

    auto load_stage = [&](int stage, int c) {
        int k0 = c * GBK;
        uint32_t sS = sbase + stage * STAGE_BYTES;
        #pragma unroll
        for (int i = 0; i < 4; i++) {
            int cid = tid + i * 256;            // 0..1023
            int row = cid >> 3, cc = cid & 7;
            uint32_t sw = (uint32_t)((cc ^ (row & 7)) << 4);
            // A rows always valid (zero-padded to PAD_ROWS)
            cp_async16(sS + row * 128 + sw,
                       g_A16 + (size_t)(tileRow + row) * IN_F + k0 + cc * 8);
            cp_async16(sS + SBH_OFF + row * 128 + sw,
                       g_Bh16 + (size_t)row * IN_F + k0 + cc * 8);
            cp_async16(sS + SBL_OFF + row * 128 + sw,
                       g_Bl16 + (size_t)row * IN_F + k0 + cc * 8);
        }
    };

    load_stage(0, 0);
    CP_COMMIT();

    const int mi = lane >> 3, r8 = lane & 7;    // ldmatrix lane decomposition

    for (int c = 0; c < NCHUNK; c++) {
        if (c + 1 < NCHUNK) load_stage((c + 1) & 1, c + 1);
        CP_COMMIT();
        CP_WAIT1();
        __syncthreads();

        uint32_t sS = sbase + (c & 1) * STAGE_BYTES;

        #pragma unroll
        for (int ks = 0; ks < 4; ks++) {
            // A fragments: loaded once, reused for both B passes
            uint32_t a[2][4];
            #pragma unroll
            for (int mt = 0; mt < 2; mt++) {
                int arow = warp_m * 32 + mt * 16 + r8 + (mi & 1) * 8;
                int ac   = ks * 2 + (mi >> 1);
                ldsm_x4(a[mt], sS + arow * 128 + ((ac ^ (arow & 7)) << 4));
            }
            #pragma unroll
            for (int p = 0; p < 2; p++) {       // Bh then Bl
                uint32_t bBase = sS + (p ? SBL_OFF : SBH_OFF);
                uint32_t b[8][2];
                #pragma unroll
                for (int np = 0; np < 4; np++) {
                    int brow = warp_n * 64 + np * 16 + (mi >> 1) * 8 + r8;
                    int bc   = ks * 2 + (mi & 1);
                    uint32_t r[4];
                    ldsm_x4(r, bBase + brow * 128 + ((bc ^ (brow & 7)) << 4));
                    b[np * 2][0]     = r[0]; b[np * 2][1]     = r[1];
                    b[np * 2 + 1][0] = r[2]; b[np * 2 + 1][1] = r[3];
                }
                #pragma unroll
                for (int mt = 0; mt < 2; mt++)
                    #pragma unroll
                    for (int nt = 0; nt < 8; nt++)
                        mma_f16(acc[mt][nt], a[mt], b[nt]);
            }
        }
        __syncthreads();
    }

    // epilogue: fp16 Wh rows
    int row0 = tileRow + warp_m * 32 + (lane >> 2);
    int col0 = warp_n * 64 + (lane & 3) * 2;
    #pragma unroll
    for (int mt = 0; mt < 2; mt++) {
        int r = row0 + mt * 16;
        #pragma unroll
        for (int nt = 0; nt < 8; nt++) {
            int cc = col0 + nt * 8;
            if (r < N_NODES)
                *(__half2*)&g_Whh[(size_t)r * OUT_F + cc] =
                    __floats2half2_rn(acc[mt][nt][0], acc[mt][nt][1]);
            if (r + 8 < N_NODES)
                *(__half2*)&g_Whh[(size_t)(r + 8) * OUT_F + cc] =
                    __floats2half2_rn(acc[mt][nt][2], acc[mt][nt][3]);
        }
    }
}

// ---------------- u1 = W @ a1, u2 = W @ a2 (warp per k row) -------------------
__global__ __launch_bounds__(256) void u_kernel(const float* __restrict__ W,
                                                const float* __restrict__ a) {
    int k    = blockIdx.x * 8 + (threadIdx.x >> 5);
    int lane = threadIdx.x & 31;
    if (k >= IN_F) return;
    float4 w  = *(const float4*)&W[(size_t)k * OUT_F + lane * 4];
    float4 a1 = *(const float4*)&a[lane * 4];
    float4 a2 = *(const float4*)&a[OUT_F + lane * 4];
    float p1 = w.x * a1.x + w.y * a1.y + w.z * a1.z + w.w * a1.w;
    float p2 = w.x * a2.x + w.y * a2.y + w.z * a2.z + w.w * a2.w;
    #pragma unroll
    for (int o = 16; o; o >>= 1) {
        p1 += __shfl_down_sync(0xFFFFFFFFu, p1, o);
        p2 += __shfl_down_sync(0xFFFFFFFFu, p2, o);
    }
    if (lane == 0) { g_u1[k] = p1; g_u2[k] = p2; }
}

// ---------------- s1 = h @ u1, s2 = h @ u2 (warp per row) ---------------------
__global__ __launch_bounds__(256) void matvec_kernel(const float* __restrict__ h) {
    __shared__ float su1[IN_F], su2[IN_F];
    int tid = threadIdx.x;
    if (tid < IN_F / 2) {
        ((float2*)su1)[tid] = ((const float2*)g_u1)[tid];
        ((float2*)su2)[tid] = ((const float2*)g_u2)[tid];
    }
    __syncthreads();
    int row  = blockIdx.x * 8 + (tid >> 5);
    int lane = tid & 31;
    if (row >= N_NODES) return;
    float p1 = 0.f, p2 = 0.f;
    #pragma unroll
    for (int i = 0; i < 4; i++) {
        float4 v  = __ldg((const float4*)&h[(size_t)row * IN_F + i * 128 + lane * 4]);
        float4 q1 = *(const float4*)&su1[i * 128 + lane * 4];
        float4 q2 = *(const float4*)&su2[i * 128 + lane * 4];
        p1 += v.x * q1.x + v.y * q1.y + v.z * q1.z + v.w * q1.w;
        p2 += v.x * q2.x + v.y * q2.y + v.z * q2.z + v.w * q2.w;
    }
    #pragma unroll
    for (int o = 16; o; o >>= 1) {
        p1 += __shfl_down_sync(0xFFFFFFFFu, p1, o);
        p2 += __shfl_down_sync(0xFFFFFFFFu, p2, o);
    }
    if (lane == 0) { g_s1[row] = p1; g_s2[row] = p2; }
}

// ---------------- dtype detection + CSR side branch ---------------------------
__global__ void detect_kernel(const int* __restrict__ ei) {
    __shared__ int any;
    if (threadIdx.x == 0) any = 0;
    __syncthreads();
    for (int i = threadIdx.x; i < 2048; i += blockDim.x)
        if (ei[2 * i + 1] != 0) any = 1;
    __syncthreads();
    if (threadIdx.x == 0) g_is64 = any ? 0 : 1;
}

__global__ void init_cnt_kernel() {
    int i = blockIdx.x * blockDim.x + threadIdx.x;
    if (i < N_NODES) g_cnt[i] = 0;
}

__device__ __forceinline__ void load_edge(const void* ei, int e, int& s, int& d) {
    if (g_is64) {
        const long long* p = (const long long*)ei;
        s = (int)p[e];
        d = (int)p[NUM_E + e];
    } else {
        const int* p = (const int*)ei;
        s = p[e];
        d = p[NUM_E + e];
    }
}

__global__ __launch_bounds__(256) void hist_kernel(const void* __restrict__ ei) {
    int e = blockIdx.x * blockDim.x + threadIdx.x;
    if (e >= NUM_E) return;
    int s, d;
    load_edge(ei, e, s, d);
    atomicAdd(&g_cnt[s], 1);
}

__global__ __launch_bounds__(256) void scan_reduce_kernel() {
    __shared__ int ws[8];
    int tid = threadIdx.x, lane = tid & 31, wid = tid >> 5;
    int s = 0;
    #pragma unroll
    for (int j = 0; j < 4; j++) {
        int i = blockIdx.x * 1024 + j * 256 + tid;
        if (i < N_NODES) s += g_cnt[i];
    }
    #pragma unroll
    for (int o = 16; o; o >>= 1) s += __shfl_xor_sync(0xFFFFFFFFu, s, o);
    if (lane == 0) ws[wid] = s;
    __syncthreads();
    if (tid == 0) {
        int t = 0;
        #pragma unroll
        for (int w = 0; w < 8; w++) t += ws[w];
        g_bsum[blockIdx.x] = t;
    }
}

__global__ void scan_mid_kernel() {
    __shared__ int w0sum;
    int t = threadIdx.x;            // 64 threads
    int lane = t & 31, w = t >> 5;
    const int NBLK = (N_NODES + 1023) / 1024;   // 49
    int v = (t < NBLK) ? g_bsum[t] : 0;
    int x = v;
    #pragma unroll
    for (int o = 1; o < 32; o <<= 1) {
        int y = __shfl_up_sync(0xFFFFFFFFu, x, o);
        if (lane >= o) x += y;
    }
    if (w == 0 && lane == 31) w0sum = x;
    __syncthreads();
    int incl = x + (w == 1 ? w0sum : 0);
    if (t < NBLK) g_boff[t] = incl - v;   // exclusive
}

__global__ __launch_bounds__(1024) void scan_final_kernel() {
    __shared__ int warpsum[32];
    int tid = threadIdx.x, lane = tid & 31, wid = tid >> 5;
    int i = blockIdx.x * 1024 + tid;
    int v = (i < N_NODES) ? g_cnt[i] : 0;
    int x = v;
    #pragma unroll
    for (int o = 1; o < 32; o <<= 1) {
        int y = __shfl_up_sync(0xFFFFFFFFu, x, o);
        if (lane >= o) x += y;
    }
    if (lane == 31) warpsum[wid] = x;
    __syncthreads();
    if (wid == 0) {
        int s = warpsum[lane];
        #pragma unroll
        for (int o = 1; o < 32; o <<= 1) {
            int y = __shfl_up_sync(0xFFFFFFFFu, s, o);
            if (lane >= o) s += y;
        }
        warpsum[lane] = s;
    }
    __syncthreads();
    int base = (wid > 0) ? warpsum[wid - 1] : 0;
    int excl = g_boff[blockIdx.x] + base + x - v;
    if (i < N_NODES) {
        g_off[i]    = excl;
        g_cursor[i] = excl;
    }
    if (blockIdx.x == 0 && tid == 0) g_off[N_NODES] = NUM_E;
}

// fill: store (dst, w = exp(logit)) — no segment max needed (range-safe)
__global__ __launch_bounds__(256) void fill_kernel(const void* __restrict__ ei) {
    int e = blockIdx.x * blockDim.x + threadIdx.x;
    if (e >= NUM_E) return;
    int s, d;
    load_edge(ei, e, s, d);
    float lg  = leaky_logit(__ldg(&g_s1[s]) + __ldg(&g_s2[d]));
    int   pos = atomicAdd(&g_cursor[s], 1);
    g_csr_dst[pos] = d;
    g_csr_w[pos]   = __expf(lg);
}

// ---------------- aggregate: warp per src node (single pass) ------------------
__global__ __launch_bounds__(256) void agg_kernel(float* __restrict__ out) {
    int src  = blockIdx.x * 8 + (threadIdx.x >> 5);
    if (src >= N_NODES) return;
    int lane = threadIdx.x & 31;
    int beg  = g_off[src];
    int end  = g_off[src + 1];

    float4* out4 = (float4*)out;
    if (beg == end) {
        out4[(size_t)src * 32 + lane] = make_float4(0.f, 0.f, 0.f, 0.f);
        return;
    }

    float ax = 0.f, ay = 0.f, az = 0.f, aw = 0.f;
    float den = 0.f;

    for (int base = beg; base < end; base += 32) {
        int  idx   = base + lane;
        bool valid = idx < end;
        int   dn = valid ? g_csr_dst[idx] : 0;
        float w  = valid ? g_csr_w[idx]   : 0.0f;
        den += w;
        int cnt = end - base;
        if (cnt >= 32) {
            #pragma unroll 8
            for (int j = 0; j < 32; j++) {
                int   dj = __shfl_sync(0xFFFFFFFFu, dn, j);
                float wj = __shfl_sync(0xFFFFFFFFu, w,  j);
                uint2 u = __ldg((const uint2*)&g_Whh[(size_t)dj * OUT_F + lane * 4]);
                float2 f0 = __half22float2(*(__half2*)&u.x);
                float2 f1 = __half22float2(*(__half2*)&u.y);
                ax += wj * f0.x; ay += wj * f0.y; az += wj * f1.x; aw += wj * f1.y;
            }
        } else {
            for (int j = 0; j < cnt; j++) {
                int   dj = __shfl_sync(0xFFFFFFFFu, dn, j);
                float wj = __shfl_sync(0xFFFFFFFFu, w,  j);
                uint2 u = __ldg((const uint2*)&g_Whh[(size_t)dj * OUT_F + lane * 4]);
                float2 f0 = __half22float2(*(__half2*)&u.x);
                float2 f1 = __half22float2(*(__half2*)&u.y);
                ax += wj * f0.x; ay += wj * f0.y; az += wj * f1.x; aw += wj * f1.y;
            }
        }
    }
    #pragma unroll
    for (int o = 16; o; o >>= 1)
        den += __shfl_xor_sync(0xFFFFFFFFu, den, o);
    float inv = (den > 0.0f) ? (1.0f / den) : 0.0f;

    float4 r;
    r.x = fmaxf(ax * inv, 0.0f);
    r.y = fmaxf(ay * inv, 0.0f);
    r.z = fmaxf(az * inv, 0.0f);
    r.w = fmaxf(aw * inv, 0.0f);
    out4[(size_t)src * 32 + lane] = r;
}

// ---------------- launch ------------------------------------------------------
extern "C" void kernel_launch(void* const* d_in, const int* in_sizes, int n_in,
                              void* d_out, int out_size) {
    const float* h  = (const float*)d_in[0];
    const float* W  = (const float*)d_in[1];
    const float* a  = (const float*)d_in[2];
    const void*  ei = d_in[3];
    float* out = (float*)d_out;

    static cudaStream_t s2 = nullptr, s3 = nullptr;
    static cudaEvent_t evFork = nullptr, evJoin = nullptr, ev3 = nullptr;
    if (s2 == nullptr) {
        cudaStreamCreateWithFlags(&s2, cudaStreamNonBlocking);
        cudaStreamCreateWithFlags(&s3, cudaStreamNonBlocking);
        cudaEventCreateWithFlags(&evFork, cudaEventDisableTiming);
        cudaEventCreateWithFlags(&evJoin, cudaEventDisableTiming);
        cudaEventCreateWithFlags(&ev3, cudaEventDisableTiming);
        cudaFuncSetAttribute(gemm_f16_kernel,
                             cudaFuncAttributeMaxDynamicSharedMemorySize, GEMM_SMEM);
    }

    const int NBLK = (N_NODES + 1023) / 1024;   // 49

    cudaEventRecord(evFork, 0);
    cudaStreamWaitEvent(s2, evFork, 0);
    cudaStreamWaitEvent(s3, evFork, 0);

    // s3: s1/s2 via associativity (u = W@a, s = h@u)
    u_kernel<<<(IN_F + 7) / 8, 256, 0, s3>>>(W, a);
    matvec_kernel<<<(N_NODES + 7) / 8, 256, 0, s3>>>(h);
    cudaEventRecord(ev3, s3);

    // s2: CSR build, then fill (needs s1/s2 from s3)
    detect_kernel<<<1, 256, 0, s2>>>((const int*)ei);
    init_cnt_kernel<<<(N_NODES + 255) / 256, 256, 0, s2>>>();
    hist_kernel<<<(NUM_E + 255) / 256, 256, 0, s2>>>(ei);
    scan_reduce_kernel<<<NBLK, 256, 0, s2>>>();
    scan_mid_kernel<<<1, 64, 0, s2>>>();
    scan_final_kernel<<<NBLK, 1024, 0, s2>>>();
    cudaStreamWaitEvent(s2, ev3, 0);
    fill_kernel<<<(NUM_E + 255) / 256, 256, 0, s2>>>(ei);
    cudaEventRecord(evJoin, s2);

    // main: converts + fp16 GEMM (concurrent with the whole side branch)
    convert_h16_kernel<<<(PAD_ROWS * (IN_F / 8) + 255) / 256, 256>>>(h);
    convert_w_kernel<<<(OUT_F * (IN_F / 8) + 255) / 256, 256>>>(W);
    gemm_f16_kernel<<<N_TILES, 256, GEMM_SMEM>>>();

    // join, then aggregate
    cudaStreamWaitEvent(0, evJoin, 0);
    agg_kernel<<<(N_NODES + 7) / 8, 256>>>(out);
}

// round 9
// speedup vs baseline: 4.5088x; 1.2610x over previous
#include <cuda_runtime.h>
#include <cuda_fp16.h>
#include <cstdint>

#define N_NODES 50000
#define NUM_E   1600000
#define IN_F    512
#define OUT_F   128
#define NEG_SLOPE 0.01f
#define INV_T     2.0f   // 1 / TEMPERATURE (0.5)

#define TILE_M   128
#define N_TILES  391                   // ceil(50000/128)
#define PAD_ROWS (N_TILES * TILE_M)    // 50048
#define GBK      64                    // K per chunk
#define NCHUNK   (IN_F / GBK)          // 8

// smem: stage = [ A 16K | Bh 16K | Bl 16K ] fp16 swizzled; double buffered
#define SBH_OFF     16384
#define SBL_OFF     32768
#define STAGE_BYTES 49152
#define GEMM_SMEM   (2 * STAGE_BYTES)  // 96 KB -> 2 CTAs/SM

// ---------------- scratch (static device globals; no allocations) -----------
__device__ __half   g_Whh[(size_t)N_NODES * OUT_F];     // 12.8 MB (fp16 Wh)
__device__ __half   g_A16[(size_t)PAD_ROWS * IN_F];     // 51.2 MB (fp16 h)
__device__ __half   g_Bh16[(size_t)OUT_F * IN_F];       // 128 KB (B^T hi fp16)
__device__ __half   g_Bl16[(size_t)OUT_F * IN_F];       // 128 KB (B^T lo fp16)
__device__ float    g_u1[IN_F];
__device__ float    g_u2[IN_F];
__device__ float    g_s1[N_NODES];
__device__ float    g_s2[N_NODES];
__device__ int      g_cnt[N_NODES];
__device__ int      g_off[N_NODES + 1];
__device__ int      g_cursor[N_NODES];
__device__ uint2    g_csr[NUM_E];                       // (dst, bits(exp(logit)))
__device__ int      g_bsum[64];
__device__ int      g_boff[64];
__device__ int      g_is64;

// ---------------- helpers ----------------------------------------------------
__device__ __forceinline__ uint32_t smem_u32(const void* p) {
    uint32_t a;
    asm("{ .reg .u64 t; cvta.to.shared.u64 t, %1; cvt.u32.u64 %0, t; }" : "=r"(a) : "l"(p));
    return a;
}
__device__ __forceinline__ void cp_async16(uint32_t dst, const void* src) {
    asm volatile("cp.async.cg.shared.global [%0], [%1], 16;"
                 :: "r"(dst), "l"(__cvta_generic_to_global(src)) : "memory");
}
#define CP_COMMIT() asm volatile("cp.async.commit_group;" ::: "memory")
#define CP_WAIT1()  asm volatile("cp.async.wait_group 1;" ::: "memory")

__device__ __forceinline__ void ldsm_x4(uint32_t* r, uint32_t addr) {
    asm volatile("ldmatrix.sync.aligned.m8n8.x4.shared.b16 {%0,%1,%2,%3}, [%4];"
                 : "=r"(r[0]), "=r"(r[1]), "=r"(r[2]), "=r"(r[3]) : "r"(addr));
}
__device__ __forceinline__ void mma_f16(float* d, const uint32_t* a, const uint32_t* b) {
    asm volatile("mma.sync.aligned.m16n8k16.row.col.f32.f16.f16.f32 "
                 "{%0,%1,%2,%3}, {%4,%5,%6,%7}, {%8,%9}, {%0,%1,%2,%3};"
                 : "+f"(d[0]), "+f"(d[1]), "+f"(d[2]), "+f"(d[3])
                 : "r"(a[0]), "r"(a[1]), "r"(a[2]), "r"(a[3]), "r"(b[0]), "r"(b[1]));
}

__device__ __forceinline__ float leaky_logit(float v) {
    v = (v >= 0.0f) ? v : NEG_SLOPE * v;
    return v * INV_T;
}

// ---------------- u1 = W @ a1, u2 = W @ a2 (warp per k row) -------------------
__global__ __launch_bounds__(256) void u_kernel(const float* __restrict__ W,
                                                const float* __restrict__ a) {
    int k    = blockIdx.x * 8 + (threadIdx.x >> 5);
    int lane = threadIdx.x & 31;
    if (k >= IN_F) return;
    float4 w  = *(const float4*)&W[(size_t)k * OUT_F + lane * 4];
    float4 a1 = *(const float4*)&a[lane * 4];
    float4 a2 = *(const float4*)&a[OUT_F + lane * 4];
    float p1 = w.x * a1.x + w.y * a1.y + w.z * a1.z + w.w * a1.w;
    float p2 = w.x * a2.x + w.y * a2.y + w.z * a2.z + w.w * a2.w;
    #pragma unroll
    for (int o = 16; o; o >>= 1) {
        p1 += __shfl_down_sync(0xFFFFFFFFu, p1, o);
        p2 += __shfl_down_sync(0xFFFFFFFFu, p2, o);
    }
    if (lane == 0) { g_u1[k] = p1; g_u2[k] = p2; }
}

// ---------------- fused: h -> fp16 A16  AND  s1/s2 = h@u1, h@u2 ---------------
// warp per row; lane l handles cols {i*128 + l*4} for i=0..3 (fully coalesced)
__global__ __launch_bounds__(256) void convmv_kernel(const float* __restrict__ h) {
    __shared__ float su1[IN_F], su2[IN_F];
    int tid = threadIdx.x;
    if (tid < IN_F / 2) {
        ((float2*)su1)[tid] = ((const float2*)g_u1)[tid];
        ((float2*)su2)[tid] = ((const float2*)g_u2)[tid];
    }
    __syncthreads();
    int row  = blockIdx.x * 8 + (tid >> 5);
    int lane = tid & 31;
    if (row >= PAD_ROWS) return;

    if (row >= N_NODES) {   // zero padded rows
        #pragma unroll
        for (int i = 0; i < 4; i++)
            *(uint2*)&g_A16[(size_t)row * IN_F + i * 128 + lane * 4] = make_uint2(0, 0);
        return;
    }

    float p1 = 0.f, p2 = 0.f;
    #pragma unroll
    for (int i = 0; i < 4; i++) {
        int col = i * 128 + lane * 4;
        float4 v  = __ldg((const float4*)&h[(size_t)row * IN_F + col]);
        float4 q1 = *(const float4*)&su1[col];
        float4 q2 = *(const float4*)&su2[col];
        p1 += v.x * q1.x + v.y * q1.y + v.z * q1.z + v.w * q1.w;
        p2 += v.x * q2.x + v.y * q2.y + v.z * q2.z + v.w * q2.w;
        __half2 h0 = __floats2half2_rn(v.x, v.y);
        __half2 h1 = __floats2half2_rn(v.z, v.w);
        uint2 q; q.x = *(uint32_t*)&h0; q.y = *(uint32_t*)&h1;
        *(uint2*)&g_A16[(size_t)row * IN_F + col] = q;
    }
    #pragma unroll
    for (int o = 16; o; o >>= 1) {
        p1 += __shfl_down_sync(0xFFFFFFFFu, p1, o);
        p2 += __shfl_down_sync(0xFFFFFFFFu, p2, o);
    }
    if (lane == 0) { g_s1[row] = p1; g_s2[row] = p2; }
}

// ---------------- W -> B^T fp16 hi/lo split ------------------------------------
__global__ __launch_bounds__(256) void convert_w_kernel(const float* __restrict__ W) {
    int idx = blockIdx.x * 256 + threadIdx.x;
    if (idx >= OUT_F * (IN_F / 8)) return;
    int n  = idx / (IN_F / 8);
    int k8 = (idx % (IN_F / 8)) * 8;
    unsigned short hb[8], lb[8];
    #pragma unroll
    for (int j = 0; j < 8; j++) {
        float v = W[(size_t)(k8 + j) * OUT_F + n];
        __half hv = __float2half_rn(v);
        __half lv = __float2half_rn(v - __half2float(hv));
        hb[j] = *(unsigned short*)&hv;
        lb[j] = *(unsigned short*)&lv;
    }
    uint4 qh, ql;
    qh.x = hb[0] | ((uint32_t)hb[1] << 16); qh.y = hb[2] | ((uint32_t)hb[3] << 16);
    qh.z = hb[4] | ((uint32_t)hb[5] << 16); qh.w = hb[6] | ((uint32_t)hb[7] << 16);
    ql.x = lb[0] | ((uint32_t)lb[1] << 16); ql.y = lb[2] | ((uint32_t)lb[3] << 16);
    ql.z = lb[4] | ((uint32_t)lb[5] << 16); ql.w = lb[6] | ((uint32_t)lb[7] << 16);
    size_t off = (size_t)n * IN_F + k8;
    *(uint4*)&g_Bh16[off] = qh;
    *(uint4*)&g_Bl16[off] = ql;
}

// ---------------- GEMM: Wh(fp16) = A16 @ (Bh + Bl) ----------------------------
__global__ __launch_bounds__(256, 2) void gemm_f16_kernel() {
    extern __shared__ char smx[];
    const int tid  = threadIdx.x;
    const int lane = tid & 31, wid = tid >> 5;
    const int warp_m = wid & 3, warp_n = wid >> 2;   // 4 x 2 warp grid
    const int tileRow = blockIdx.x * TILE_M;
    const uint32_t sbase = smem_u32(smx);

    float acc[2][8][4];
    #pragma unroll
    for (int mt = 0; mt < 2; mt++)
        #pragma unroll
        for (int nt = 0; nt < 8; nt++)
            #pragma unroll
            for (int q = 0; q < 4; q++) acc[mt][nt][q] = 0.0f;

    auto load_stage = [&](int stage, int c) {
        int k0 = c * GBK;
        uint32_t sS = sbase + stage * STAGE_BYTES;
        #pragma unroll
        for (int i = 0; i < 4; i++) {
            int cid = tid + i * 256;            // 0..1023
            int row = cid >> 3, cc = cid & 7;
            uint32_t sw = (uint32_t)((cc ^ (row & 7)) << 4);
            cp_async16(sS + row * 128 + sw,
                       g_A16 + (size_t)(tileRow + row) * IN_F + k0 + cc * 8);
            cp_async16(sS + SBH_OFF + row * 128 + sw,
                       g_Bh16 + (size_t)row * IN_F + k0 + cc * 8);
            cp_async16(sS + SBL_OFF + row * 128 + sw,
                       g_Bl16 + (size_t)row * IN_F + k0 + cc * 8);
        }
    };

    load_stage(0, 0);
    CP_COMMIT();

    const int mi = lane >> 3, r8 = lane & 7;

    for (int c = 0; c < NCHUNK; c++) {
        if (c + 1 < NCHUNK) load_stage((c + 1) & 1, c + 1);
        CP_COMMIT();
        CP_WAIT1();
        __syncthreads();

        uint32_t sS = sbase + (c & 1) * STAGE_BYTES;

        #pragma unroll
        for (int ks = 0; ks < 4; ks++) {
            uint32_t a[2][4];
            #pragma unroll
            for (int mt = 0; mt < 2; mt++) {
                int arow = warp_m * 32 + mt * 16 + r8 + (mi & 1) * 8;
                int ac   = ks * 2 + (mi >> 1);
                ldsm_x4(a[mt], sS + arow * 128 + ((ac ^ (arow & 7)) << 4));
            }
            #pragma unroll
            for (int p = 0; p < 2; p++) {       // Bh then Bl
                uint32_t bBase = sS + (p ? SBL_OFF : SBH_OFF);
                uint32_t b[8][2];
                #pragma unroll
                for (int np = 0; np < 4; np++) {
                    int brow = warp_n * 64 + np * 16 + (mi >> 1) * 8 + r8;
                    int bc   = ks * 2 + (mi & 1);
                    uint32_t r[4];
                    ldsm_x4(r, bBase + brow * 128 + ((bc ^ (brow & 7)) << 4));
                    b[np * 2][0]     = r[0]; b[np * 2][1]     = r[1];
                    b[np * 2 + 1][0] = r[2]; b[np * 2 + 1][1] = r[3];
                }
                #pragma unroll
                for (int mt = 0; mt < 2; mt++)
                    #pragma unroll
                    for (int nt = 0; nt < 8; nt++)
                        mma_f16(acc[mt][nt], a[mt], b[nt]);
            }
        }
        __syncthreads();
    }

    int row0 = tileRow + warp_m * 32 + (lane >> 2);
    int col0 = warp_n * 64 + (lane & 3) * 2;
    #pragma unroll
    for (int mt = 0; mt < 2; mt++) {
        int r = row0 + mt * 16;
        #pragma unroll
        for (int nt = 0; nt < 8; nt++) {
            int cc = col0 + nt * 8;
            if (r < N_NODES)
                *(__half2*)&g_Whh[(size_t)r * OUT_F + cc] =
                    __floats2half2_rn(acc[mt][nt][0], acc[mt][nt][1]);
            if (r + 8 < N_NODES)
                *(__half2*)&g_Whh[(size_t)(r + 8) * OUT_F + cc] =
                    __floats2half2_rn(acc[mt][nt][2], acc[mt][nt][3]);
        }
    }
}

// ---------------- dtype detection + CSR side branch ---------------------------
__global__ void detect_kernel(const int* __restrict__ ei) {
    __shared__ int any;
    if (threadIdx.x == 0) any = 0;
    __syncthreads();
    for (int i = threadIdx.x; i < 2048; i += blockDim.x)
        if (ei[2 * i + 1] != 0) any = 1;
    __syncthreads();
    if (threadIdx.x == 0) g_is64 = any ? 0 : 1;
}

__global__ void init_cnt_kernel() {
    int i = blockIdx.x * blockDim.x + threadIdx.x;
    if (i < N_NODES) g_cnt[i] = 0;
}

__device__ __forceinline__ void load_edge(const void* ei, int e, int& s, int& d) {
    if (g_is64) {
        const long long* p = (const long long*)ei;
        s = (int)p[e];
        d = (int)p[NUM_E + e];
    } else {
        const int* p = (const int*)ei;
        s = p[e];
        d = p[NUM_E + e];
    }
}

__global__ __launch_bounds__(256) void hist_kernel(const void* __restrict__ ei) {
    int e = blockIdx.x * blockDim.x + threadIdx.x;
    if (e >= NUM_E) return;
    int s, d;
    load_edge(ei, e, s, d);
    atomicAdd(&g_cnt[s], 1);
}

__global__ __launch_bounds__(256) void scan_reduce_kernel() {
    __shared__ int ws[8];
    int tid = threadIdx.x, lane = tid & 31, wid = tid >> 5;
    int s = 0;
    #pragma unroll
    for (int j = 0; j < 4; j++) {
        int i = blockIdx.x * 1024 + j * 256 + tid;
        if (i < N_NODES) s += g_cnt[i];
    }
    #pragma unroll
    for (int o = 16; o; o >>= 1) s += __shfl_xor_sync(0xFFFFFFFFu, s, o);
    if (lane == 0) ws[wid] = s;
    __syncthreads();
    if (tid == 0) {
        int t = 0;
        #pragma unroll
        for (int w = 0; w < 8; w++) t += ws[w];
        g_bsum[blockIdx.x] = t;
    }
}

__global__ void scan_mid_kernel() {
    __shared__ int w0sum;
    int t = threadIdx.x;            // 64 threads
    int lane = t & 31, w = t >> 5;
    const int NBLK = (N_NODES + 1023) / 1024;   // 49
    int v = (t < NBLK) ? g_bsum[t] : 0;
    int x = v;
    #pragma unroll
    for (int o = 1; o < 32; o <<= 1) {
        int y = __shfl_up_sync(0xFFFFFFFFu, x, o);
        if (lane >= o) x += y;
    }
    if (w == 0 && lane == 31) w0sum = x;
    __syncthreads();
    int incl = x + (w == 1 ? w0sum : 0);
    if (t < NBLK) g_boff[t] = incl - v;   // exclusive
}

__global__ __launch_bounds__(1024) void scan_final_kernel() {
    __shared__ int warpsum[32];
    int tid = threadIdx.x, lane = tid & 31, wid = tid >> 5;
    int i = blockIdx.x * 1024 + tid;
    int v = (i < N_NODES) ? g_cnt[i] : 0;
    int x = v;
    #pragma unroll
    for (int o = 1; o < 32; o <<= 1) {
        int y = __shfl_up_sync(0xFFFFFFFFu, x, o);
        if (lane >= o) x += y;
    }
    if (lane == 31) warpsum[wid] = x;
    __syncthreads();
    if (wid == 0) {
        int s = warpsum[lane];
        #pragma unroll
        for (int o = 1; o < 32; o <<= 1) {
            int y = __shfl_up_sync(0xFFFFFFFFu, s, o);
            if (lane >= o) s += y;
        }
        warpsum[lane] = s;
    }
    __syncthreads();
    int base = (wid > 0) ? warpsum[wid - 1] : 0;
    int excl = g_boff[blockIdx.x] + base + x - v;
    if (i < N_NODES) {
        g_off[i]    = excl;
        g_cursor[i] = excl;
    }
    if (blockIdx.x == 0 && tid == 0) g_off[N_NODES] = NUM_E;
}

// fill: packed CSR record (dst, bits(exp(logit)))
__global__ __launch_bounds__(256) void fill_kernel(const void* __restrict__ ei) {
    int e = blockIdx.x * blockDim.x + threadIdx.x;
    if (e >= NUM_E) return;
    int s, d;
    load_edge(ei, e, s, d);
    float lg  = leaky_logit(__ldg(&g_s1[s]) + __ldg(&g_s2[d]));
    int   pos = atomicAdd(&g_cursor[s], 1);
    g_csr[pos] = make_uint2((unsigned)d, __float_as_uint(__expf(lg)));
}

// ---------------- aggregate: warp per node, half-warp per edge ----------------
// lane = half*16 + l16; lane loads 16B (8 fp16 feats) of Whh row; halves take
// even/odd edges of each 32-edge batch -> serial chain halved vs 1 edge/step.
__global__ __launch_bounds__(256) void agg_kernel(float* __restrict__ out) {
    int src  = blockIdx.x * 8 + (threadIdx.x >> 5);
    if (src >= N_NODES) return;
    int lane = threadIdx.x & 31;
    int l16  = lane & 15;
    int half = (lane >> 4) & 1;
    int beg  = g_off[src];
    int end  = g_off[src + 1];

    float4* out4 = (float4*)out;
    if (beg == end) {
        if (lane < 16) {
            out4[(size_t)src * 32 + l16 * 2]     = make_float4(0.f, 0.f, 0.f, 0.f);
            out4[(size_t)src * 32 + l16 * 2 + 1] = make_float4(0.f, 0.f, 0.f, 0.f);
        }
        return;
    }

    float acc[8];
    #pragma unroll
    for (int i = 0; i < 8; i++) acc[i] = 0.0f;
    float den = 0.f;

    for (int base = beg; base < end; base += 32) {
        int  idx   = base + lane;
        bool valid = idx < end;
        uint2 rec = valid ? __ldg(&g_csr[idx]) : make_uint2(0u, 0u);
        int   dn  = (int)rec.x;
        float w   = valid ? __uint_as_float(rec.y) : 0.0f;
        den += w;
        int cnt   = min(end - base, 32);
        int iters = (cnt + 1) >> 1;
        #pragma unroll 4
        for (int j = 0; j < iters; j++) {
            int   sl = 2 * j + half;
            int   dj = __shfl_sync(0xFFFFFFFFu, dn, sl);
            float wj = __shfl_sync(0xFFFFFFFFu, w,  sl);
            uint4 u = __ldg((const uint4*)&g_Whh[(size_t)dj * OUT_F + l16 * 8]);
            float2 f0 = __half22float2(*(__half2*)&u.x);
            float2 f1 = __half22float2(*(__half2*)&u.y);
            float2 f2 = __half22float2(*(__half2*)&u.z);
            float2 f3 = __half22float2(*(__half2*)&u.w);
            acc[0] += wj * f0.x; acc[1] += wj * f0.y;
            acc[2] += wj * f1.x; acc[3] += wj * f1.y;
            acc[4] += wj * f2.x; acc[5] += wj * f2.y;
            acc[6] += wj * f3.x; acc[7] += wj * f3.y;
        }
    }

    // combine halves (same features, disjoint edge subsets)
    #pragma unroll
    for (int i = 0; i < 8; i++)
        acc[i] += __shfl_xor_sync(0xFFFFFFFFu, acc[i], 16);
    #pragma unroll
    for (int o = 16; o; o >>= 1)
        den += __shfl_xor_sync(0xFFFFFFFFu, den, o);
    float inv = (den > 0.0f) ? (1.0f / den) : 0.0f;

    if (lane < 16) {
        float4 r0, r1;
        r0.x = fmaxf(acc[0] * inv, 0.0f); r0.y = fmaxf(acc[1] * inv, 0.0f);
        r0.z = fmaxf(acc[2] * inv, 0.0f); r0.w = fmaxf(acc[3] * inv, 0.0f);
        r1.x = fmaxf(acc[4] * inv, 0.0f); r1.y = fmaxf(acc[5] * inv, 0.0f);
        r1.z = fmaxf(acc[6] * inv, 0.0f); r1.w = fmaxf(acc[7] * inv, 0.0f);
        out4[(size_t)src * 32 + l16 * 2]     = r0;
        out4[(size_t)src * 32 + l16 * 2 + 1] = r1;
    }
}

// ---------------- launch ------------------------------------------------------
extern "C" void kernel_launch(void* const* d_in, const int* in_sizes, int n_in,
                              void* d_out, int out_size) {
    const float* h  = (const float*)d_in[0];
    const float* W  = (const float*)d_in[1];
    const float* a  = (const float*)d_in[2];
    const void*  ei = d_in[3];
    float* out = (float*)d_out;

    static cudaStream_t s2 = nullptr;
    static cudaEvent_t evFork = nullptr, evJoin = nullptr, evMv = nullptr;
    if (s2 == nullptr) {
        cudaStreamCreateWithFlags(&s2, cudaStreamNonBlocking);
        cudaEventCreateWithFlags(&evFork, cudaEventDisableTiming);
        cudaEventCreateWithFlags(&evJoin, cudaEventDisableTiming);
        cudaEventCreateWithFlags(&evMv, cudaEventDisableTiming);
        cudaFuncSetAttribute(gemm_f16_kernel,
                             cudaFuncAttributeMaxDynamicSharedMemorySize, GEMM_SMEM);
    }

    const int NBLK = (N_NODES + 1023) / 1024;   // 49

    cudaEventRecord(evFork, 0);
    cudaStreamWaitEvent(s2, evFork, 0);

    // s2: CSR build (edge_index only)
    detect_kernel<<<1, 256, 0, s2>>>((const int*)ei);
    init_cnt_kernel<<<(N_NODES + 255) / 256, 256, 0, s2>>>();
    hist_kernel<<<(NUM_E + 255) / 256, 256, 0, s2>>>(ei);
    scan_reduce_kernel<<<NBLK, 256, 0, s2>>>();
    scan_mid_kernel<<<1, 64, 0, s2>>>();
    scan_final_kernel<<<NBLK, 1024, 0, s2>>>();

    // main: u -> fused convert+matvec -> convert_w -> gemm
    u_kernel<<<(IN_F + 7) / 8, 256>>>(W, a);
    convmv_kernel<<<(PAD_ROWS + 7) / 8, 256>>>(h);
    cudaEventRecord(evMv, 0);   // s1/s2 + A16 ready
    convert_w_kernel<<<(OUT_F * (IN_F / 8) + 255) / 256, 256>>>(W);
    gemm_f16_kernel<<<N_TILES, 256, GEMM_SMEM>>>();

    // s2: fill once s1/s2 ready (overlaps gemm)
    cudaStreamWaitEvent(s2, evMv, 0);
    fill_kernel<<<(NUM_E + 255) / 256, 256, 0, s2>>>(ei);
    cudaEventRecord(evJoin, s2);

    // join, then aggregate
    cudaStreamWaitEvent(0, evJoin, 0);
    agg_kernel<<<(N_NODES + 7) / 8, 256>>>(out);
}